// round 6
// baseline (speedup 1.0000x reference)
#include <cuda_runtime.h>
#include <math.h>

#define BB 32
#define SS 32
#define TT 31
#define HH 256
#define H3 768
#define VV 12000
#define NTOK 32
#define BOUND 16
#define ATP 1024   // padded row length of g_attT
#define NCH 32     // chain shard CTAs per group

// ---------------- metadata (written by control kernel) ----------------
__device__ signed char g_la[TT][BB];
__device__ signed char g_npop[TT][BB];
__device__ signed char g_pop_slot[TT][BB][SS];
__device__ signed char g_pop_tok[TT][BB][SS];
__device__ signed char g_spush_slot[TT][BB];   // -1 none
__device__ signed char g_spush_tok[TT][BB];    // -1 = rfinal value, >=0 token
__device__ signed char g_bpush_tok[TT][BB];    // -1 none
__device__ signed char g_stop[TT][BB];         // stack top after step

// precomputed token xw tables: set 0=a,1=b,2=s,3=r
__device__ __align__(16) float g_tokxw[4][NTOK][H3];
// attention outputs TRANSPOSED: [hidden c][row], row = b*TT + t; zero padding
__device__ __align__(16) float g_attT[HH][ATP];

// chain outputs (write-once per launch step; counters reset every launch)
__device__ __align__(16) float g_ahs[TT][BB][HH];
__device__ __align__(16) float g_bufs[TT][BB][HH];
__device__ __align__(16) float g_pah[TT][BB][HH];
__device__ __align__(16) float g_pb[TT][BB][HH];
__device__ int g_hdone_a[TT];
__device__ int g_pdone_a[TT];
__device__ int g_hdone_b[TT];
__device__ int g_pdone_b[TT];

// ---------------- small asm helpers ----------------
__device__ __forceinline__ unsigned long long pk2(float lo, float hi) {
    unsigned long long r;
    asm("mov.b64 %0, {%1, %2};" : "=l"(r) : "f"(lo), "f"(hi));
    return r;
}
__device__ __forceinline__ void upk2(float& lo, float& hi, unsigned long long v) {
    asm("mov.b64 {%0, %1}, %2;" : "=f"(lo), "=f"(hi) : "l"(v));
}
__device__ __forceinline__ void ffma2(unsigned long long& d, unsigned long long a,
                                      unsigned long long b) {
    asm("fma.rn.f32x2 %0, %1, %2, %3;" : "=l"(d) : "l"(a), "l"(b), "l"(d));
}
__device__ __forceinline__ unsigned smem_u32(const void* p) {
    return (unsigned)__cvta_generic_to_shared(p);
}
__device__ __forceinline__ void st_peer(unsigned addr, unsigned peer, float v) {
    unsigned pa;
    asm volatile("mapa.shared::cluster.u32 %0, %1, %2;" : "=r"(pa) : "r"(addr), "r"(peer));
    asm volatile("st.shared::cluster.f32 [%0], %1;" :: "r"(pa), "f"(v) : "memory");
}
#define CLUSTER_SYNC() do { \
    asm volatile("barrier.cluster.arrive.aligned;" ::: "memory"); \
    asm volatile("barrier.cluster.wait.aligned;" ::: "memory"); } while (0)

#define CP16(dst, src) \
    asm volatile("cp.async.cg.shared.global [%0], [%1], 16;" :: "r"(dst), "l"(src))
#define CP_COMMIT() asm volatile("cp.async.commit_group;" ::: "memory")

__device__ __forceinline__ float sigm(float v) { return 1.f / (1.f + expf(-v)); }

// ---------------- control kernel: pure integer RNNG simulation ----------------
__global__ void control_kernel(const int* __restrict__ actions) {
    int b = threadIdx.x;
    // reset chain counters for this launch (graph-replay safe)
    if (b < TT) {
        g_hdone_a[b] = 0; g_pdone_a[b] = 0;
        g_hdone_b[b] = 0; g_pdone_b[b] = 0;
    }
    int st = -1, tt_ = -1, bt = 0, acc = 1;  // bt=0 after initial buffer push
    signed char tm[SS];
    signed char stok[SS];

    for (int t = 0; t < TT; t++) {
        int a = actions[b * SS + t];
        int la = a * acc;
        int is_red = (la == 2) ? 1 : 0;
        int is_nt  = (la > 2 && la < BOUND) ? 1 : 0;
        int is_gen = (la >= BOUND) ? 1 : 0;

        int np = 0;
        int ir = is_red, aok = 1;
        for (int i = 0; i < SS; i++) {
            if (!(ir && aok)) break;
            int can1 = (st >= 0);
            int pslot = -1;
            if (can1) { pslot = st; st--; }
            aok = aok & can1;
            int tag = 0;
            if (ir && aok) {
                int can2 = (tt_ >= 0);
                if (can2) { tag = tm[tt_]; tt_--; }
                aok = aok & can2;
            }
            int outm = ir & aok;
            if (outm) {
                g_pop_slot[t][b][np] = (signed char)pslot;
                g_pop_tok[t][b][np]  = stok[pslot];
                np++;
            }
            ir = (ir - tag) * aok;
        }
        int racc = aok;
        int sslot = -1, stokv = -2;
        if (is_red && racc) {
            int can = (st + 1 < SS);
            if (can) { st++; sslot = st; stokv = -1; stok[st] = -1; }
            racc &= can;
            if (racc) {
                int can2 = (tt_ + 1 < SS);
                if (can2) { tt_++; tm[tt_] = 0; }
                racc &= can2;
            }
        }
        unsigned ball = __ballot_sync(0xffffffffu, is_red);
        int tot = np;
        for (int o = 16; o > 0; o >>= 1) tot += __shfl_xor_sync(0xffffffffu, tot, o);
        int red_mult = 1;
        if (ball) red_mult = (tot == 0) ? 0 : racc;
        acc *= red_mult;

        if (is_nt) {
            int s5 = (st + 1 < SS);
            if (s5) { st++; stok[st] = (signed char)la; sslot = st; stokv = la; }
            acc *= s5;
            if (s5) {
                int s6 = (tt_ + 1 < SS);
                if (s6) { tt_++; tm[tt_] = 1; }
                acc *= s6;
            }
        }
        int bpush = -1;
        if (is_gen) {
            int s7 = (st + 1 < SS);
            if (s7) { st++; stok[st] = (signed char)la; sslot = st; stokv = la; }
            acc *= s7;
            int s8 = 1;
            if (s7) {
                s8 = (tt_ + 1 < SS);
                if (s8) { tt_++; tm[tt_] = 0; }
                acc *= s8;
            }
            if (s7 && s8) {
                int s9 = (bt + 1 < SS);
                if (s9) { bt++; bpush = la; }
                acc *= s9;
            }
        }
        g_bpush_tok[t][b]  = (signed char)bpush;
        g_la[t][b]         = (signed char)la;
        g_npop[t][b]       = (signed char)np;
        g_spush_slot[t][b] = (signed char)sslot;
        g_spush_tok[t][b]  = (signed char)stokv;
        g_stop[t][b]       = (signed char)st;
    }
}

// ---------------- token xw tables ----------------
__global__ void tokxw_kernel(const float* __restrict__ embed,
                             const float* __restrict__ aW, const float* __restrict__ ab,
                             const float* __restrict__ bW, const float* __restrict__ bb,
                             const float* __restrict__ sW, const float* __restrict__ sb,
                             const float* __restrict__ rW, const float* __restrict__ rb) {
    int tok = blockIdx.x;
    int set = blockIdx.y;
    const float* W  = (set == 0) ? aW : (set == 1) ? bW : (set == 2) ? sW : rW;
    const float* bi = (set == 0) ? ab : (set == 1) ? bb : (set == 2) ? sb : rb;
    int tid = threadIdx.x;  // 192 threads, 1 float4 col each
    const float4* W4 = (const float4*)W;
    float4 acc = __ldg((const float4*)bi + tid);
    const float* x = embed + (size_t)tok * HH;
#pragma unroll 8
    for (int k = 0; k < HH; k++) {
        float xk = __ldg(x + k);
        float4 w = __ldg(W4 + k * 192 + tid);
        acc.x += xk * w.x; acc.y += xk * w.y; acc.z += xk * w.z; acc.w += xk * w.w;
    }
    ((float4*)(&g_tokxw[set][tok][0]))[tid] = acc;
}

// ---------------- half matvec: this CTA's 384 of 768 cols ----------------
__device__ __forceinline__ void mv_half(const float* __restrict__ M, const float* __restrict__ x,
                                        float* out, const float* __restrict__ bias,
                                        int tid, int rank, float* part) {
    __syncthreads();
    int w = tid >> 5, l = tid & 31;
    const float4* M4 = (const float4*)M + (size_t)(w * 32) * 192 + rank * 32;
    const float* xs = x + w * 32;
    float4 a0 = make_float4(0.f, 0.f, 0.f, 0.f), a1 = a0, a2 = a0;
#pragma unroll 2
    for (int k = 0; k < 32; k++) {
        float xk = xs[k];
        const float4* row = M4 + k * 192;
        float4 m0 = __ldg(row + l);
        float4 m1 = __ldg(row + 64 + l);
        float4 m2 = __ldg(row + 128 + l);
        a0.x += xk * m0.x; a0.y += xk * m0.y; a0.z += xk * m0.z; a0.w += xk * m0.w;
        a1.x += xk * m1.x; a1.y += xk * m1.y; a1.z += xk * m1.z; a1.w += xk * m1.w;
        a2.x += xk * m2.x; a2.y += xk * m2.y; a2.z += xk * m2.z; a2.w += xk * m2.w;
    }
    float4* p4 = (float4*)part + w * 96;
    p4[l] = a0; p4[32 + l] = a1; p4[64 + l] = a2;
    __syncthreads();
    if (tid < 128) {
#pragma unroll
        for (int g = 0; g < 3; g++) {
            int c = g * 256 + rank * 128 + tid;
            float s = bias ? __ldg(bias + c) : 0.f;
#pragma unroll
            for (int w2 = 0; w2 < 8; w2++) s += part[w2 * 384 + g * 128 + tid];
            out[c] = s;
        }
    }
}

// half piece matvec: out[tid<128] = (x @ Wpiece)[rank*128 + tid]
__device__ __forceinline__ void piece_half(const float* __restrict__ W, const float* __restrict__ x,
                                           float* out, int tid, int rank, float* part) {
    __syncthreads();
    int w = tid >> 5, l = tid & 31;
    const float4* W4 = (const float4*)W + (size_t)(w * 32) * 64 + rank * 32;
    const float* xs = x + w * 32;
    float4 a = make_float4(0.f, 0.f, 0.f, 0.f);
#pragma unroll 4
    for (int k = 0; k < 32; k++) {
        float xk = xs[k];
        float4 m = __ldg(W4 + k * 64 + l);
        a.x += xk * m.x; a.y += xk * m.y; a.z += xk * m.z; a.w += xk * m.w;
    }
    ((float4*)part)[w * 32 + l] = a;
    __syncthreads();
    if (tid < 128) {
        float s = 0.f;
#pragma unroll
        for (int w2 = 0; w2 < 8; w2++) s += part[w2 * 128 + tid];
        out[tid] = s;
    }
}

// ---------------- fused kernel: 64 main CTAs (2/lane) + 64 chain CTAs ----------------
extern __shared__ float smem_f[];
__global__ __launch_bounds__(256) __cluster_dims__(2, 1, 1)
void main_kernel(
    const float* __restrict__ aU, const float* __restrict__ bU,
    const float* __restrict__ sU, const float* __restrict__ rU,
    const float* __restrict__ sW, const float* __restrict__ sb,
    const float* __restrict__ rW, const float* __restrict__ rb,
    const float* __restrict__ Wc, const float* __restrict__ bc) {
    int tid = threadIdx.x;

    if (blockIdx.x >= 2 * BB) {
        // ================= chain shard CTA =================
        int cb  = blockIdx.x - 2 * BB;      // 0..63
        int grp = cb >> 5;                  // 0 = ah chain, 1 = buf chain
        int sh  = cb & 31;                  // shard 0..31
        int lane = tid & 31, ci = tid >> 5;
        int c = sh * 8 + ci;                // owned hidden column
        const float* U   = grp ? bU : aU;
        const float* WcP = Wc + (size_t)(grp ? 512 : 256) * HH;
        int* hdone = grp ? g_hdone_b : g_hdone_a;
        int* pdone = grp ? g_pdone_b : g_pdone_a;
        float (*gst)[BB][HH] = grp ? g_bufs : g_ahs;
        float (*gp)[BB][HH]  = grp ? g_pb  : g_pah;
        float* xT = smem_f;                 // [256][33]

        float h = 0.f;
        if (grp == 1) {
            // initial buffer push state: gate(tokxw_b[1], 0); same for all lanes
            const float* xw = &g_tokxw[1][1][0];
            h = sigm(xw[c]) * tanhf(xw[2 * HH + c]);
            for (int k = tid; k < HH; k += 256) {
                float v = sigm(xw[k]) * tanhf(xw[2 * HH + k]);
#pragma unroll 8
                for (int l2 = 0; l2 < 32; l2++) xT[k * 33 + l2] = v;
            }
            __syncthreads();
        }

        for (int t = 0; t < TT; t++) {
            bool have_hu = (grp == 1) || (t > 0);
            float hz = 0.f, hr = 0.f, hn = 0.f;
            if (have_hu) {
#pragma unroll 4
                for (int k = 0; k < HH; k++) {
                    float xv = xT[k * 33 + lane];
                    hz += xv * __ldg(U + (size_t)k * H3 + c);
                    hr += xv * __ldg(U + (size_t)k * H3 + HH + c);
                    hn += xv * __ldg(U + (size_t)k * H3 + 2 * HH + c);
                }
            }
            int tok = (grp == 0) ? (int)g_la[t][lane] : (int)g_bpush_tok[t][lane];
            bool do_gate = (grp == 0) ? true : (tok >= 0);
            if (do_gate) {
                const float* xw = &g_tokxw[grp][tok][0];
                float z = sigm(xw[c] + hz);
                float r = sigm(xw[HH + c] + hr);
                float n = tanhf(xw[2 * HH + c] + r * hn);
                float hp = have_hu ? h : 0.f;
                h = (1.f - z) * hp + z * n;
            }
            gst[t][lane][c] = h;
            __threadfence();
            __syncthreads();
            if (tid == 0) {
                atomicAdd(&hdone[t], 1);
                while (*(volatile int*)&hdone[t] < NCH) { }
            }
            __syncthreads();
            // reload full state xT(t) (transposed, pad 33)
#pragma unroll
            for (int i = 0; i < 8; i++) {
                int idx = tid + i * 256;      // float4 index 0..2047
                int l2 = idx >> 6, k4 = idx & 63;
                float4 v = *(const float4*)&gst[t][l2][k4 * 4];
                xT[(k4 * 4 + 0) * 33 + l2] = v.x;
                xT[(k4 * 4 + 1) * 33 + l2] = v.y;
                xT[(k4 * 4 + 2) * 33 + l2] = v.z;
                xT[(k4 * 4 + 3) * 33 + l2] = v.w;
            }
            __syncthreads();
            // attention piece for owned column
            float pv = 0.f;
#pragma unroll 4
            for (int k = 0; k < HH; k++)
                pv += xT[k * 33 + lane] * __ldg(WcP + (size_t)k * HH + c);
            gp[t][lane][c] = pv;
            __threadfence();
            __syncthreads();
            if (tid == 0) atomicAdd(&pdone[t], 1);
        }
        return;
    }

    // ================= main (stack system) CTA =================
    int b = blockIdx.x >> 1;
    int rank = blockIdx.x & 1;
    unsigned peer = (unsigned)(rank ^ 1);

    float* sm_v = smem_f;            // [32][256] stack values (rfinal slots)
    float* hs   = sm_v + SS * HH;    // [32][256] hidden-state stack
    float* hred = hs + SS * HH;      // [256]
    float* s_hu = hred + HH;         // [768]
    float* s_xw = s_hu + H3;         // [768]
    float* part = s_xw + H3;         // [8*384] scratch
    float* p_s  = part + 8 * 384;    // [128]

    unsigned base_u32 = smem_u32(smem_f);
    unsigned hs_a   = base_u32 + (unsigned)((char*)hs - (char*)smem_f);
    unsigned hred_a = base_u32 + (unsigned)((char*)hred - (char*)smem_f);

    if (tid < 128) p_s[tid] = 0.f;
    __syncthreads();

    int prev_stop = -1;

    for (int t = 0; t < TT; t++) {
        int np    = g_npop[t][b];
        int sslot = g_spush_slot[t][b];
        int stokv = g_spush_tok[t][b];
        int stop  = g_stop[t][b];

        // ---- reduce chain ----
        for (int i = 0; i < np; i++) {
            int slot = g_pop_slot[t][b][i];
            int tok  = g_pop_tok[t][b][i];
            if (tok >= 0 && i == 0) {
                const float* xw = &g_tokxw[3][tok][0];
                __syncthreads();
                hred[tid] = sigm(xw[tid]) * tanhf(xw[2 * HH + tid]);
                __syncthreads();
            } else {
                const float* xw;
                if (tok >= 0) xw = &g_tokxw[3][tok][0];
                else { mv_half(rW, &sm_v[slot * HH], s_xw, rb, tid, rank, part); xw = s_xw; }
                if (i > 0) mv_half(rU, hred, s_hu, nullptr, tid, rank, part);
                if (tid < 128) {
                    int c = rank * 128 + tid;
                    float hz = 0.f, hr = 0.f, hn = 0.f, hp = 0.f;
                    if (i > 0) { hz = s_hu[c]; hr = s_hu[HH + c]; hn = s_hu[2 * HH + c]; hp = hred[c]; }
                    float z = sigm(xw[c] + hz);
                    float r = sigm(xw[HH + c] + hr);
                    float n = tanhf(xw[2 * HH + c] + r * hn);
                    float h = (1.f - z) * hp + z * n;
                    hred[c] = h;
                    st_peer(hred_a + (unsigned)c * 4, peer, h);
                }
                CLUSTER_SYNC();
            }
        }

        // ---- stack push ----
        if (sslot >= 0) {
            const float* xw_s;
            if (stokv >= 0) {
                xw_s = &g_tokxw[2][stokv][0];
            } else {
                __syncthreads();
                sm_v[sslot * HH + tid] = hred[tid];
                mv_half(sW, hred, s_xw, sb, tid, rank, part);
                xw_s = s_xw;
            }
            if (sslot > 0) mv_half(sU, &hs[(sslot - 1) * HH], s_hu, nullptr, tid, rank, part);
            if (tid < 128) {
                int c = rank * 128 + tid;
                float hz = 0.f, hr = 0.f, hn = 0.f, hp = 0.f;
                if (sslot > 0) {
                    hz = s_hu[c]; hr = s_hu[HH + c]; hn = s_hu[2 * HH + c];
                    hp = hs[(sslot - 1) * HH + c];
                }
                float z = sigm(xw_s[c] + hz);
                float r = sigm(xw_s[HH + c] + hr);
                float n = tanhf(xw_s[2 * HH + c] + r * hn);
                float h = (1.f - z) * hp + z * n;
                hs[sslot * HH + c] = h;
                st_peer(hs_a + (unsigned)(sslot * HH + c) * 4, peer, h);
            }
        }
        CLUSTER_SYNC();   // hs halves exchanged

        // ---- attention ----
        {
            bool s_dirty = (stop != prev_stop) || (sslot >= 0);
            if (s_dirty) {
                if (stop < 0) {
                    __syncthreads();
                    if (tid < 128) p_s[tid] = 0.f;
                } else {
                    piece_half(Wc, &hs[stop * HH], p_s, tid, rank, part);
                }
            }
            if (tid == 0) {
                while (*(volatile int*)&g_pdone_a[t] < NCH) { }
                while (*(volatile int*)&g_pdone_b[t] < NCH) { }
            }
            __syncthreads();
            if (tid < 128) {
                int c = rank * 128 + tid;
                float v = p_s[tid] + g_pah[t][b][c] + g_pb[t][b][c] + __ldg(bc + c);
                g_attT[c][b * TT + t] = tanhf(v);
            }
            prev_stop = stop;
        }
        CLUSTER_SYNC();
    }
}

// ---------------- logits GEMM: cp.async double-buffered, f32x2 FFMA ----------------
#define GBM 128
#define GBN 128
#define GBK 16
__global__ __launch_bounds__(256, 2) void gemm_kernel(const float* __restrict__ Wp,
                                                      const float* __restrict__ bp,
                                                      float* __restrict__ out) {
    __shared__ float As[2][GBK][GBM];
    __shared__ float Bs[2][GBK][GBN];
    int tid = threadIdx.x;
    int c0 = blockIdx.x * GBN;
    int row0 = blockIdx.y * GBM;
    const int MROWS = BB * TT;
    const float* attT = &g_attT[0][0];

    unsigned sA = smem_u32(&As[0][0][0]);
    unsigned sB = smem_u32(&Bs[0][0][0]);

    int ty = tid >> 4, tx = tid & 15;

    unsigned long long accp[8][4];
#pragma unroll
    for (int i = 0; i < 8; i++)
#pragma unroll
        for (int j = 0; j < 4; j++) accp[i][j] = 0ull;

    const int NTILE = HH / GBK;

#define ISSUE_TILE(buf, kk) do {                                              \
        _Pragma("unroll")                                                     \
        for (int i_ = 0; i_ < 2; i_++) {                                      \
            int idx_ = tid * 2 + i_;                                          \
            int k_ = idx_ >> 5;                                               \
            int q_ = idx_ & 31;                                               \
            unsigned da_ = sA + (unsigned)((((buf) * GBK + k_) * GBM + q_ * 4) * 4); \
            CP16(da_, attT + (size_t)((kk) + k_) * ATP + row0 + q_ * 4);      \
            int gc_ = c0 + q_ * 4;                                            \
            if (gc_ + 3 < VV) {                                               \
                unsigned db_ = sB + (unsigned)((((buf) * GBK + k_) * GBN + q_ * 4) * 4); \
                CP16(db_, Wp + (size_t)((kk) + k_) * VV + gc_);               \
            } else {                                                          \
                float4 z4_ = make_float4(0.f, 0.f, 0.f, 0.f);                 \
                *(float4*)&Bs[buf][k_][q_ * 4] = z4_;                         \
            }                                                                 \
        }                                                                     \
        CP_COMMIT();                                                          \
    } while (0)

    ISSUE_TILE(0, 0);
    for (int tIdx = 0; tIdx < NTILE; tIdx++) {
        int buf = tIdx & 1;
        if (tIdx + 1 < NTILE) {
            ISSUE_TILE((tIdx + 1) & 1, (tIdx + 1) * GBK);
            asm volatile("cp.async.wait_group 1;" ::: "memory");
        } else {
            asm volatile("cp.async.wait_group 0;" ::: "memory");
        }
        __syncthreads();
#pragma unroll
        for (int k = 0; k < GBK; k++) {
            float4 a01 = *((const float4*)&As[buf][k][ty * 8]);
            float4 a23 = *((const float4*)&As[buf][k][ty * 8 + 4]);
            float4 b01 = *((const float4*)&Bs[buf][k][tx * 8]);
            float4 b23 = *((const float4*)&Bs[buf][k][tx * 8 + 4]);
            unsigned long long brp[4];
            brp[0] = pk2(b01.x, b01.y); brp[1] = pk2(b01.z, b01.w);
            brp[2] = pk2(b23.x, b23.y); brp[3] = pk2(b23.z, b23.w);
            float ar[8] = {a01.x, a01.y, a01.z, a01.w, a23.x, a23.y, a23.z, a23.w};
#pragma unroll
            for (int i = 0; i < 8; i++) {
                unsigned long long ap = pk2(ar[i], ar[i]);
                ffma2(accp[i][0], ap, brp[0]);
                ffma2(accp[i][1], ap, brp[1]);
                ffma2(accp[i][2], ap, brp[2]);
                ffma2(accp[i][3], ap, brp[3]);
            }
        }
        __syncthreads();
    }

    float bias[8];
#pragma unroll
    for (int j = 0; j < 8; j++) {
        int gc = c0 + tx * 8 + j;
        bias[j] = (gc < VV) ? __ldg(bp + gc) : 0.f;
    }
#pragma unroll
    for (int i = 0; i < 8; i++) {
        int grow = row0 + ty * 8 + i;
        if (grow >= MROWS) continue;
        int gc = c0 + tx * 8;
        float acc[8];
#pragma unroll
        for (int j = 0; j < 4; j++) upk2(acc[2 * j], acc[2 * j + 1], accp[i][j]);
        if (gc + 7 < VV) {
            float4 o0 = make_float4(acc[0] + bias[0], acc[1] + bias[1],
                                    acc[2] + bias[2], acc[3] + bias[3]);
            float4 o1 = make_float4(acc[4] + bias[4], acc[5] + bias[5],
                                    acc[6] + bias[6], acc[7] + bias[7]);
            *((float4*)(out + (size_t)grow * VV + gc)) = o0;
            *((float4*)(out + (size_t)grow * VV + gc + 4)) = o1;
        } else {
#pragma unroll
            for (int j = 0; j < 8; j++)
                if (gc + j < VV) out[(size_t)grow * VV + gc + j] = acc[j] + bias[j];
        }
    }
}

// ---------------- argmax per row ----------------
__global__ void argmax_kernel(const float* __restrict__ logits, float* __restrict__ preds) {
    int row = blockIdx.x;
    int tid = threadIdx.x;
    const float* p = logits + (size_t)row * VV;
    float best = -3.4e38f;
    int bi = VV;
    for (int c = tid; c < VV; c += 256) {
        float v = p[c];
        if (v > best) { best = v; bi = c; }
    }
    __shared__ float sv[256];
    __shared__ int si[256];
    sv[tid] = best; si[tid] = bi;
    __syncthreads();
    for (int o = 128; o > 0; o >>= 1) {
        if (tid < o) {
            if (sv[tid + o] > sv[tid] || (sv[tid + o] == sv[tid] && si[tid + o] < si[tid])) {
                sv[tid] = sv[tid + o]; si[tid] = si[tid + o];
            }
        }
        __syncthreads();
    }
    if (tid == 0) preds[row] = (float)si[0];
}

// ---------------- launch ----------------
extern "C" void kernel_launch(void* const* d_in, const int* in_sizes, int n_in,
                              void* d_out, int out_size) {
    const int*   actions = (const int*)d_in[0];
    const float* embed = (const float*)d_in[1];
    const float* aW = (const float*)d_in[2];
    const float* aU = (const float*)d_in[3];
    const float* ab = (const float*)d_in[4];
    const float* bW = (const float*)d_in[5];
    const float* bU = (const float*)d_in[6];
    const float* bb = (const float*)d_in[7];
    const float* sW = (const float*)d_in[8];
    const float* sU = (const float*)d_in[9];
    const float* sb = (const float*)d_in[10];
    const float* rW = (const float*)d_in[11];
    const float* rU = (const float*)d_in[12];
    const float* rb = (const float*)d_in[13];
    const float* Wc = (const float*)d_in[14];
    const float* bc = (const float*)d_in[15];
    const float* Wp = (const float*)d_in[16];
    const float* bp = (const float*)d_in[17];

    float* outf = (float*)d_out;
    size_t nl = (size_t)BB * TT * VV;
    float* preds = nullptr;
    float* logits;
    if ((size_t)out_size >= nl + (size_t)BB * TT) {
        preds = outf;
        logits = outf + BB * TT;
    } else {
        logits = outf;
    }

    control_kernel<<<1, 32>>>(actions);
    tokxw_kernel<<<dim3(NTOK, 4), 192>>>(embed, aW, ab, bW, bb, sW, sb, rW, rb);

    // smem: sm_v(8192) + hs(8192) + hred(256) + s_hu(768) + s_xw(768)
    //       + part(3072) + p_s(128) = 21376 floats; chain xT needs 8448 <= this
    size_t shbytes = 21376u * sizeof(float);
    cudaFuncSetAttribute(main_kernel, cudaFuncAttributeMaxDynamicSharedMemorySize, (int)shbytes);
    main_kernel<<<2 * BB + 2 * NCH, 256, shbytes>>>(aU, bU, sU, rU, sW, sb, rW, rb, Wc, bc);

    dim3 gg((VV + GBN - 1) / GBN, (BB * TT + GBM - 1) / GBM);
    gemm_kernel<<<gg, 256>>>(Wp, bp, logits);
    if (preds) argmax_kernel<<<BB * TT, 256>>>(logits, preds);
}

// round 7
// speedup vs baseline: 1.7974x; 1.7974x over previous
#include <cuda_runtime.h>
#include <math.h>

#define BB 32
#define SS 32
#define TT 31
#define HH 256
#define H3 768
#define VV 12000
#define NTOK 32
#define BOUND 16
#define ATP 1024   // padded row length of g_attT
#define NCH 16     // chain shard CTAs per group

// ---------------- metadata (written by control kernel) ----------------
__device__ signed char g_la[TT][BB];
__device__ signed char g_npop[TT][BB];
__device__ signed char g_pop_slot[TT][BB][SS];
__device__ signed char g_pop_tok[TT][BB][SS];
__device__ signed char g_spush_slot[TT][BB];   // -1 none
__device__ signed char g_spush_tok[TT][BB];    // -1 = rfinal value, >=0 token
__device__ signed char g_bpush_tok[TT][BB];    // -1 none
__device__ signed char g_stop[TT][BB];         // stack top after step

// precomputed token xw tables: set 0=a,1=b,2=s,3=r
__device__ __align__(16) float g_tokxw[4][NTOK][H3];
// attention outputs TRANSPOSED: [hidden c][row], row = b*TT + t; zero padding
__device__ __align__(16) float g_attT[HH][ATP];

// chain outputs (write-once per launch step; counters reset every launch)
__device__ __align__(16) float g_ahs[TT][BB][HH];
__device__ __align__(16) float g_bufs[TT][BB][HH];
__device__ __align__(16) float g_pah[TT][BB][HH];
__device__ __align__(16) float g_pb[TT][BB][HH];
__device__ int g_hdone_a[TT];
__device__ int g_pdone_a[TT];
__device__ int g_hdone_b[TT];
__device__ int g_pdone_b[TT];

// ---------------- small asm helpers ----------------
__device__ __forceinline__ unsigned long long pk2(float lo, float hi) {
    unsigned long long r;
    asm("mov.b64 %0, {%1, %2};" : "=l"(r) : "f"(lo), "f"(hi));
    return r;
}
__device__ __forceinline__ void upk2(float& lo, float& hi, unsigned long long v) {
    asm("mov.b64 {%0, %1}, %2;" : "=f"(lo), "=f"(hi) : "l"(v));
}
__device__ __forceinline__ void ffma2(unsigned long long& d, unsigned long long a,
                                      unsigned long long b) {
    asm("fma.rn.f32x2 %0, %1, %2, %3;" : "=l"(d) : "l"(a), "l"(b), "l"(d));
}
__device__ __forceinline__ unsigned smem_u32(const void* p) {
    return (unsigned)__cvta_generic_to_shared(p);
}
__device__ __forceinline__ void st_peer(unsigned addr, unsigned peer, float v) {
    unsigned pa;
    asm volatile("mapa.shared::cluster.u32 %0, %1, %2;" : "=r"(pa) : "r"(addr), "r"(peer));
    asm volatile("st.shared::cluster.f32 [%0], %1;" :: "r"(pa), "f"(v) : "memory");
}
#define CLUSTER_SYNC() do { \
    asm volatile("barrier.cluster.arrive.aligned;" ::: "memory"); \
    asm volatile("barrier.cluster.wait.aligned;" ::: "memory"); } while (0)

#define CP16(dst, src) \
    asm volatile("cp.async.cg.shared.global [%0], [%1], 16;" :: "r"(dst), "l"(src))
#define CP_COMMIT() asm volatile("cp.async.commit_group;" ::: "memory")

__device__ __forceinline__ float sigm(float v) { return 1.f / (1.f + expf(-v)); }

// ---------------- control kernel: pure integer RNNG simulation ----------------
__global__ void control_kernel(const int* __restrict__ actions) {
    int b = threadIdx.x;
    if (b < TT) {   // reset chain flags every launch (graph-replay safe)
        g_hdone_a[b] = 0; g_pdone_a[b] = 0;
        g_hdone_b[b] = 0; g_pdone_b[b] = 0;
    }
    int st = -1, tt_ = -1, bt = 0, acc = 1;  // bt=0 after initial buffer push
    signed char tm[SS];
    signed char stok[SS];

    for (int t = 0; t < TT; t++) {
        int a = actions[b * SS + t];
        int la = a * acc;
        int is_red = (la == 2) ? 1 : 0;
        int is_nt  = (la > 2 && la < BOUND) ? 1 : 0;
        int is_gen = (la >= BOUND) ? 1 : 0;

        int np = 0;
        int ir = is_red, aok = 1;
        for (int i = 0; i < SS; i++) {
            if (!(ir && aok)) break;
            int can1 = (st >= 0);
            int pslot = -1;
            if (can1) { pslot = st; st--; }
            aok = aok & can1;
            int tag = 0;
            if (ir && aok) {
                int can2 = (tt_ >= 0);
                if (can2) { tag = tm[tt_]; tt_--; }
                aok = aok & can2;
            }
            int outm = ir & aok;
            if (outm) {
                g_pop_slot[t][b][np] = (signed char)pslot;
                g_pop_tok[t][b][np]  = stok[pslot];
                np++;
            }
            ir = (ir - tag) * aok;
        }
        int racc = aok;
        int sslot = -1, stokv = -2;
        if (is_red && racc) {
            int can = (st + 1 < SS);
            if (can) { st++; sslot = st; stokv = -1; stok[st] = -1; }
            racc &= can;
            if (racc) {
                int can2 = (tt_ + 1 < SS);
                if (can2) { tt_++; tm[tt_] = 0; }
                racc &= can2;
            }
        }
        unsigned ball = __ballot_sync(0xffffffffu, is_red);
        int tot = np;
        for (int o = 16; o > 0; o >>= 1) tot += __shfl_xor_sync(0xffffffffu, tot, o);
        int red_mult = 1;
        if (ball) red_mult = (tot == 0) ? 0 : racc;
        acc *= red_mult;

        if (is_nt) {
            int s5 = (st + 1 < SS);
            if (s5) { st++; stok[st] = (signed char)la; sslot = st; stokv = la; }
            acc *= s5;
            if (s5) {
                int s6 = (tt_ + 1 < SS);
                if (s6) { tt_++; tm[tt_] = 1; }
                acc *= s6;
            }
        }
        int bpush = -1;
        if (is_gen) {
            int s7 = (st + 1 < SS);
            if (s7) { st++; stok[st] = (signed char)la; sslot = st; stokv = la; }
            acc *= s7;
            int s8 = 1;
            if (s7) {
                s8 = (tt_ + 1 < SS);
                if (s8) { tt_++; tm[tt_] = 0; }
                acc *= s8;
            }
            if (s7 && s8) {
                int s9 = (bt + 1 < SS);
                if (s9) { bt++; bpush = la; }
                acc *= s9;
            }
        }
        g_bpush_tok[t][b]  = (signed char)bpush;
        g_la[t][b]         = (signed char)la;
        g_npop[t][b]       = (signed char)np;
        g_spush_slot[t][b] = (signed char)sslot;
        g_spush_tok[t][b]  = (signed char)stokv;
        g_stop[t][b]       = (signed char)st;
    }
}

// ---------------- token xw tables ----------------
__global__ void tokxw_kernel(const float* __restrict__ embed,
                             const float* __restrict__ aW, const float* __restrict__ ab,
                             const float* __restrict__ bW, const float* __restrict__ bb,
                             const float* __restrict__ sW, const float* __restrict__ sb,
                             const float* __restrict__ rW, const float* __restrict__ rb) {
    int tok = blockIdx.x;
    int set = blockIdx.y;
    const float* W  = (set == 0) ? aW : (set == 1) ? bW : (set == 2) ? sW : rW;
    const float* bi = (set == 0) ? ab : (set == 1) ? bb : (set == 2) ? sb : rb;
    int tid = threadIdx.x;  // 192 threads
    const float4* W4 = (const float4*)W;
    float4 acc = __ldg((const float4*)bi + tid);
    const float* x = embed + (size_t)tok * HH;
#pragma unroll 8
    for (int k = 0; k < HH; k++) {
        float xk = __ldg(x + k);
        float4 w = __ldg(W4 + k * 192 + tid);
        acc.x += xk * w.x; acc.y += xk * w.y; acc.z += xk * w.z; acc.w += xk * w.w;
    }
    ((float4*)(&g_tokxw[set][tok][0]))[tid] = acc;
}

// ---------------- half matvec: this CTA's 384 of 768 cols ----------------
__device__ __forceinline__ void mv_half(const float* __restrict__ M, const float* __restrict__ x,
                                        float* out, const float* __restrict__ bias,
                                        int tid, int rank, float* part) {
    __syncthreads();
    int w = tid >> 5, l = tid & 31;
    const float4* M4 = (const float4*)M + (size_t)(w * 32) * 192 + rank * 32;
    const float* xs = x + w * 32;
    float4 a0 = make_float4(0.f, 0.f, 0.f, 0.f), a1 = a0, a2 = a0;
#pragma unroll 2
    for (int k = 0; k < 32; k++) {
        float xk = xs[k];
        const float4* row = M4 + k * 192;
        float4 m0 = __ldg(row + l);
        float4 m1 = __ldg(row + 64 + l);
        float4 m2 = __ldg(row + 128 + l);
        a0.x += xk * m0.x; a0.y += xk * m0.y; a0.z += xk * m0.z; a0.w += xk * m0.w;
        a1.x += xk * m1.x; a1.y += xk * m1.y; a1.z += xk * m1.z; a1.w += xk * m1.w;
        a2.x += xk * m2.x; a2.y += xk * m2.y; a2.z += xk * m2.z; a2.w += xk * m2.w;
    }
    float4* p4 = (float4*)part + w * 96;
    p4[l] = a0; p4[32 + l] = a1; p4[64 + l] = a2;
    __syncthreads();
    if (tid < 128) {
#pragma unroll
        for (int g = 0; g < 3; g++) {
            int c = g * 256 + rank * 128 + tid;
            float s = bias ? __ldg(bias + c) : 0.f;
#pragma unroll
            for (int w2 = 0; w2 < 8; w2++) s += part[w2 * 384 + g * 128 + tid];
            out[c] = s;
        }
    }
}

// half piece matvec: out[tid<128] = (x @ Wpiece)[rank*128 + tid]
__device__ __forceinline__ void piece_half(const float* __restrict__ W, const float* __restrict__ x,
                                           float* out, int tid, int rank, float* part) {
    __syncthreads();
    int w = tid >> 5, l = tid & 31;
    const float4* W4 = (const float4*)W + (size_t)(w * 32) * 64 + rank * 32;
    const float* xs = x + w * 32;
    float4 a = make_float4(0.f, 0.f, 0.f, 0.f);
#pragma unroll 4
    for (int k = 0; k < 32; k++) {
        float xk = xs[k];
        float4 m = __ldg(W4 + k * 64 + l);
        a.x += xk * m.x; a.y += xk * m.y; a.z += xk * m.z; a.w += xk * m.w;
    }
    ((float4*)part)[w * 32 + l] = a;
    __syncthreads();
    if (tid < 128) {
        float s = 0.f;
#pragma unroll
        for (int w2 = 0; w2 < 8; w2++) s += part[w2 * 128 + tid];
        out[tid] = s;
    }
}

// ---------------- fused kernel: 64 main CTAs + 32 chain CTAs ----------------
extern __shared__ float smem_f[];
__global__ __launch_bounds__(256) __cluster_dims__(2, 1, 1)
void main_kernel(
    const float* __restrict__ aU, const float* __restrict__ bU,
    const float* __restrict__ sU, const float* __restrict__ rU,
    const float* __restrict__ sW, const float* __restrict__ sb,
    const float* __restrict__ rW, const float* __restrict__ rb,
    const float* __restrict__ Wc, const float* __restrict__ bc) {
    int tid = threadIdx.x;

    if (blockIdx.x >= 2 * BB) {
        // ================= chain shard CTA (weights SMEM-resident) =================
        int cb  = blockIdx.x - 2 * BB;   // 0..31
        int grp = cb >> 4;               // 0 = ah chain, 1 = buf chain
        int sh  = cb & 15;               // owns hidden cols [sh*16, sh*16+16)
        int c0  = sh * 16;
        const float* U = grp ? bU : aU;
        float* Uslc = smem_f;            // [256][48]
        float* Wslc = smem_f + 12288;    // [256][16]
        float* xT   = smem_f + 16384;    // [256][32]  state transposed [k][lane]
        float* stg  = smem_f + 24576;    // [1536]
        int* hdone = grp ? g_hdone_b : g_hdone_a;
        int* pdone = grp ? g_pdone_b : g_pdone_a;
        float (*gst)[BB][HH] = grp ? g_bufs : g_ahs;
        float (*gp)[BB][HH]  = grp ? g_pb  : g_pah;

        // preload U slice (gate cols {c, 256+c, 512+c} for owned c)
        const float4* U4 = (const float4*)U;
        for (int idx = tid; idx < 256 * 12; idx += 256) {
            int k = idx / 12, f = idx % 12;
            int g = f >> 2, q = f & 3;
            float4 v = __ldg(U4 + (size_t)k * 192 + g * 64 + (c0 >> 2) + q);
            *((float4*)&Uslc[k * 48 + g * 16 + q * 4]) = v;
        }
        // preload Wc piece slice [256][16]
        const float* WcP = Wc + (size_t)(256 + grp * 256) * HH;
        for (int idx = tid; idx < 256 * 4; idx += 256) {
            int k = idx >> 2, q = idx & 3;
            float4 v = __ldg((const float4*)(WcP + (size_t)k * HH + c0) + q);
            *((float4*)&Wslc[k * 16 + q * 4]) = v;
        }
        // init state
        if (grp == 0) {
            for (int i = tid; i < 8192; i += 256) xT[i] = 0.f;
        } else {
            const float* xw1 = &g_tokxw[1][1][0];
            for (int k = tid; k < HH; k += 256) {
                float v = sigm(xw1[k]) * tanhf(xw1[2 * HH + k]);
#pragma unroll 8
                for (int l = 0; l < 32; l++) xT[k * 32 + l] = v;
            }
        }
        __syncthreads();

        int kh = tid >> 7;          // k-half
        int lb = (tid >> 4) & 7;    // lane block (4 lanes)
        int gc = tid & 15;          // owned col index
        int l0 = lb * 4;
        int c  = c0 + gc;

        for (int t = 0; t < TT; t++) {
            float hz[4] = {0.f, 0.f, 0.f, 0.f};
            float hr[4] = {0.f, 0.f, 0.f, 0.f};
            float hn[4] = {0.f, 0.f, 0.f, 0.f};
            bool have_hu = (grp == 1) || (t > 0);
            if (have_hu) {
                int k0 = kh * 128;
#pragma unroll 4
                for (int k = k0; k < k0 + 128; k++) {
                    float w0 = Uslc[k * 48 + gc];
                    float w1 = Uslc[k * 48 + 16 + gc];
                    float w2 = Uslc[k * 48 + 32 + gc];
#pragma unroll
                    for (int j = 0; j < 4; j++) {
                        float x = xT[k * 32 + l0 + j];
                        hz[j] += x * w0; hr[j] += x * w1; hn[j] += x * w2;
                    }
                }
            }
            if (kh == 1) {
                float* s = &stg[(lb * 16 + gc) * 12];
#pragma unroll
                for (int j = 0; j < 4; j++) { s[j] = hz[j]; s[4 + j] = hr[j]; s[8 + j] = hn[j]; }
            }
            __syncthreads();
            if (kh == 0) {
                float* s = &stg[(lb * 16 + gc) * 12];
#pragma unroll
                for (int j = 0; j < 4; j++) { hz[j] += s[j]; hr[j] += s[4 + j]; hn[j] += s[8 + j]; }
#pragma unroll
                for (int j = 0; j < 4; j++) {
                    int lane = l0 + j;
                    int tok = grp ? (int)g_bpush_tok[t][lane] : (int)g_la[t][lane];
                    float hp = xT[c * 32 + lane];
                    float h;
                    if (grp == 1 && tok < 0) {
                        h = hp;
                    } else {
                        const float* xw = &g_tokxw[grp][tok][0];
                        float z = sigm(xw[c] + hz[j]);
                        float r = sigm(xw[HH + c] + hr[j]);
                        float n = tanhf(xw[2 * HH + c] + r * hn[j]);
                        h = (1.f - z) * (have_hu ? hp : 0.f) + z * n;
                    }
                    gst[t][lane][c] = h;
                }
            }
            __threadfence();
            __syncthreads();
            if (tid == 0) {
                atomicAdd(&hdone[t], 1);
                while (atomicAdd(&hdone[t], 0) < NCH) { }
            }
            __syncthreads();
            // reload full state transposed
            for (int i = tid; i < 2048; i += 256) {
                int l = i >> 6, k4 = i & 63;
                float4 v = *(const float4*)&gst[t][l][k4 * 4];
                xT[(k4 * 4 + 0) * 32 + l] = v.x;
                xT[(k4 * 4 + 1) * 32 + l] = v.y;
                xT[(k4 * 4 + 2) * 32 + l] = v.z;
                xT[(k4 * 4 + 3) * 32 + l] = v.w;
            }
            __syncthreads();
            // attention piece for owned cols
            float pv[4] = {0.f, 0.f, 0.f, 0.f};
            {
                int k0 = kh * 128;
#pragma unroll 4
                for (int k = k0; k < k0 + 128; k++) {
                    float w = Wslc[k * 16 + gc];
#pragma unroll
                    for (int j = 0; j < 4; j++) pv[j] += xT[k * 32 + l0 + j] * w;
                }
            }
            if (kh == 1) {
                float* s = &stg[(lb * 16 + gc) * 4];
#pragma unroll
                for (int j = 0; j < 4; j++) s[j] = pv[j];
            }
            __syncthreads();
            if (kh == 0) {
                float* s = &stg[(lb * 16 + gc) * 4];
#pragma unroll
                for (int j = 0; j < 4; j++) gp[t][l0 + j][c] = pv[j] + s[j];
            }
            __threadfence();
            __syncthreads();
            if (tid == 0) atomicAdd(&pdone[t], 1);
        }
        return;
    }

    // ================= main (stack system) CTA — round-5 structure =================
    int b = blockIdx.x >> 1;
    int rank = blockIdx.x & 1;
    unsigned peer = (unsigned)(rank ^ 1);

    float* sm_v = smem_f;            // [32][256]
    float* hs   = sm_v + SS * HH;    // [32][256]
    float* hred = hs + SS * HH;      // [256]
    float* s_hu = hred + HH;         // [768]
    float* s_xw = s_hu + H3;         // [768]
    float* part = s_xw + H3;         // [8*384]
    float* p_s  = part + 8 * 384;    // [128]

    unsigned base_u32 = smem_u32(smem_f);
    unsigned hs_a   = base_u32 + (unsigned)((char*)hs - (char*)smem_f);
    unsigned hred_a = base_u32 + (unsigned)((char*)hred - (char*)smem_f);

    if (tid < 128) p_s[tid] = 0.f;
    __syncthreads();

    int prev_stop = -1;

    for (int t = 0; t < TT; t++) {
        int np    = g_npop[t][b];
        int sslot = g_spush_slot[t][b];
        int stokv = g_spush_tok[t][b];
        int stop  = g_stop[t][b];

        // ---- reduce chain ----
        for (int i = 0; i < np; i++) {
            int slot = g_pop_slot[t][b][i];
            int tok  = g_pop_tok[t][b][i];
            if (tok >= 0 && i == 0) {
                const float* xw = &g_tokxw[3][tok][0];
                __syncthreads();
                hred[tid] = sigm(xw[tid]) * tanhf(xw[2 * HH + tid]);
                __syncthreads();
            } else {
                const float* xw;
                if (tok >= 0) xw = &g_tokxw[3][tok][0];
                else { mv_half(rW, &sm_v[slot * HH], s_xw, rb, tid, rank, part); xw = s_xw; }
                if (i > 0) mv_half(rU, hred, s_hu, nullptr, tid, rank, part);
                if (tid < 128) {
                    int c = rank * 128 + tid;
                    float hz = 0.f, hr = 0.f, hn = 0.f, hp = 0.f;
                    if (i > 0) { hz = s_hu[c]; hr = s_hu[HH + c]; hn = s_hu[2 * HH + c]; hp = hred[c]; }
                    float z = sigm(xw[c] + hz);
                    float r = sigm(xw[HH + c] + hr);
                    float n = tanhf(xw[2 * HH + c] + r * hn);
                    float h = (1.f - z) * hp + z * n;
                    hred[c] = h;
                    st_peer(hred_a + (unsigned)c * 4, peer, h);
                }
                CLUSTER_SYNC();
            }
        }

        // ---- stack push ----
        if (sslot >= 0) {
            const float* xw_s;
            if (stokv >= 0) {
                xw_s = &g_tokxw[2][stokv][0];
            } else {
                __syncthreads();
                sm_v[sslot * HH + tid] = hred[tid];
                mv_half(sW, hred, s_xw, sb, tid, rank, part);
                xw_s = s_xw;
            }
            if (sslot > 0) mv_half(sU, &hs[(sslot - 1) * HH], s_hu, nullptr, tid, rank, part);
            if (tid < 128) {
                int c = rank * 128 + tid;
                float hz = 0.f, hr = 0.f, hn = 0.f, hp = 0.f;
                if (sslot > 0) {
                    hz = s_hu[c]; hr = s_hu[HH + c]; hn = s_hu[2 * HH + c];
                    hp = hs[(sslot - 1) * HH + c];
                }
                float z = sigm(xw_s[c] + hz);
                float r = sigm(xw_s[HH + c] + hr);
                float n = tanhf(xw_s[2 * HH + c] + r * hn);
                float h = (1.f - z) * hp + z * n;
                hs[sslot * HH + c] = h;
                st_peer(hs_a + (unsigned)(sslot * HH + c) * 4, peer, h);
            }
        }
        CLUSTER_SYNC();   // hs halves exchanged

        // ---- attention: local p_s + chain-published p_ah/p_b ----
        {
            bool s_dirty = (stop != prev_stop) || (sslot >= 0);
            if (s_dirty) {
                if (stop < 0) {
                    __syncthreads();
                    if (tid < 128) p_s[tid] = 0.f;
                } else {
                    piece_half(Wc, &hs[stop * HH], p_s, tid, rank, part);
                }
            }
            if (tid == 0) {
                while (atomicAdd(&g_pdone_a[t], 0) < NCH) { }
                while (atomicAdd(&g_pdone_b[t], 0) < NCH) { }
                __threadfence();
            }
            __syncthreads();
            if (tid < 128) {
                int c = rank * 128 + tid;
                float v = p_s[tid] + g_pah[t][b][c] + g_pb[t][b][c] + __ldg(bc + c);
                g_attT[c][b * TT + t] = tanhf(v);
            }
            prev_stop = stop;
        }
        CLUSTER_SYNC();
    }
}

// ---------------- logits GEMM: cp.async double-buffered, f32x2 FFMA ----------------
#define GBM 128
#define GBN 128
#define GBK 16
__global__ __launch_bounds__(256, 2) void gemm_kernel(const float* __restrict__ Wp,
                                                      const float* __restrict__ bp,
                                                      float* __restrict__ out) {
    __shared__ float As[2][GBK][GBM];
    __shared__ float Bs[2][GBK][GBN];
    int tid = threadIdx.x;
    int c0 = blockIdx.x * GBN;
    int row0 = blockIdx.y * GBM;
    const int MROWS = BB * TT;
    const float* attT = &g_attT[0][0];

    unsigned sA = smem_u32(&As[0][0][0]);
    unsigned sB = smem_u32(&Bs[0][0][0]);

    int ty = tid >> 4, tx = tid & 15;

    unsigned long long accp[8][4];
#pragma unroll
    for (int i = 0; i < 8; i++)
#pragma unroll
        for (int j = 0; j < 4; j++) accp[i][j] = 0ull;

    const int NTILE = HH / GBK;

#define ISSUE_TILE(buf, kk) do {                                              \
        _Pragma("unroll")                                                     \
        for (int i_ = 0; i_ < 2; i_++) {                                      \
            int idx_ = tid * 2 + i_;                                          \
            int k_ = idx_ >> 5;                                               \
            int q_ = idx_ & 31;                                               \
            unsigned da_ = sA + (unsigned)((((buf) * GBK + k_) * GBM + q_ * 4) * 4); \
            CP16(da_, attT + (size_t)((kk) + k_) * ATP + row0 + q_ * 4);      \
            int gc_ = c0 + q_ * 4;                                            \
            if (gc_ + 3 < VV) {                                               \
                unsigned db_ = sB + (unsigned)((((buf) * GBK + k_) * GBN + q_ * 4) * 4); \
                CP16(db_, Wp + (size_t)((kk) + k_) * VV + gc_);               \
            } else {                                                          \
                float4 z4_ = make_float4(0.f, 0.f, 0.f, 0.f);                 \
                *(float4*)&Bs[buf][k_][q_ * 4] = z4_;                         \
            }                                                                 \
        }                                                                     \
        CP_COMMIT();                                                          \
    } while (0)

    ISSUE_TILE(0, 0);
    for (int tIdx = 0; tIdx < NTILE; tIdx++) {
        int buf = tIdx & 1;
        if (tIdx + 1 < NTILE) {
            ISSUE_TILE((tIdx + 1) & 1, (tIdx + 1) * GBK);
            asm volatile("cp.async.wait_group 1;" ::: "memory");
        } else {
            asm volatile("cp.async.wait_group 0;" ::: "memory");
        }
        __syncthreads();
#pragma unroll
        for (int k = 0; k < GBK; k++) {
            float4 a01 = *((const float4*)&As[buf][k][ty * 8]);
            float4 a23 = *((const float4*)&As[buf][k][ty * 8 + 4]);
            float4 b01 = *((const float4*)&Bs[buf][k][tx * 8]);
            float4 b23 = *((const float4*)&Bs[buf][k][tx * 8 + 4]);
            unsigned long long brp[4];
            brp[0] = pk2(b01.x, b01.y); brp[1] = pk2(b01.z, b01.w);
            brp[2] = pk2(b23.x, b23.y); brp[3] = pk2(b23.z, b23.w);
            float ar[8] = {a01.x, a01.y, a01.z, a01.w, a23.x, a23.y, a23.z, a23.w};
#pragma unroll
            for (int i = 0; i < 8; i++) {
                unsigned long long ap = pk2(ar[i], ar[i]);
                ffma2(accp[i][0], ap, brp[0]);
                ffma2(accp[i][1], ap, brp[1]);
                ffma2(accp[i][2], ap, brp[2]);
                ffma2(accp[i][3], ap, brp[3]);
            }
        }
        __syncthreads();
    }

    float bias[8];
#pragma unroll
    for (int j = 0; j < 8; j++) {
        int gc = c0 + tx * 8 + j;
        bias[j] = (gc < VV) ? __ldg(bp + gc) : 0.f;
    }
#pragma unroll
    for (int i = 0; i < 8; i++) {
        int grow = row0 + ty * 8 + i;
        if (grow >= MROWS) continue;
        int gc = c0 + tx * 8;
        float acc[8];
#pragma unroll
        for (int j = 0; j < 4; j++) upk2(acc[2 * j], acc[2 * j + 1], accp[i][j]);
        if (gc + 7 < VV) {
            float4 o0 = make_float4(acc[0] + bias[0], acc[1] + bias[1],
                                    acc[2] + bias[2], acc[3] + bias[3]);
            float4 o1 = make_float4(acc[4] + bias[4], acc[5] + bias[5],
                                    acc[6] + bias[6], acc[7] + bias[7]);
            *((float4*)(out + (size_t)grow * VV + gc)) = o0;
            *((float4*)(out + (size_t)grow * VV + gc + 4)) = o1;
        } else {
#pragma unroll
            for (int j = 0; j < 8; j++)
                if (gc + j < VV) out[(size_t)grow * VV + gc + j] = acc[j] + bias[j];
        }
    }
}

// ---------------- argmax per row ----------------
__global__ void argmax_kernel(const float* __restrict__ logits, float* __restrict__ preds) {
    int row = blockIdx.x;
    int tid = threadIdx.x;
    const float* p = logits + (size_t)row * VV;
    float best = -3.4e38f;
    int bi = VV;
    for (int c = tid; c < VV; c += 256) {
        float v = p[c];
        if (v > best) { best = v; bi = c; }
    }
    __shared__ float sv[256];
    __shared__ int si[256];
    sv[tid] = best; si[tid] = bi;
    __syncthreads();
    for (int o = 128; o > 0; o >>= 1) {
        if (tid < o) {
            if (sv[tid + o] > sv[tid] || (sv[tid + o] == sv[tid] && si[tid + o] < si[tid])) {
                sv[tid] = sv[tid + o]; si[tid] = si[tid + o];
            }
        }
        __syncthreads();
    }
    if (tid == 0) preds[row] = (float)si[0];
}

// ---------------- launch ----------------
extern "C" void kernel_launch(void* const* d_in, const int* in_sizes, int n_in,
                              void* d_out, int out_size) {
    const int*   actions = (const int*)d_in[0];
    const float* embed = (const float*)d_in[1];
    const float* aW = (const float*)d_in[2];
    const float* aU = (const float*)d_in[3];
    const float* ab = (const float*)d_in[4];
    const float* bW = (const float*)d_in[5];
    const float* bU = (const float*)d_in[6];
    const float* bb = (const float*)d_in[7];
    const float* sW = (const float*)d_in[8];
    const float* sU = (const float*)d_in[9];
    const float* sb = (const float*)d_in[10];
    const float* rW = (const float*)d_in[11];
    const float* rU = (const float*)d_in[12];
    const float* rb = (const float*)d_in[13];
    const float* Wc = (const float*)d_in[14];
    const float* bc = (const float*)d_in[15];
    const float* Wp = (const float*)d_in[16];
    const float* bp = (const float*)d_in[17];

    float* outf = (float*)d_out;
    size_t nl = (size_t)BB * TT * VV;
    float* preds = nullptr;
    float* logits;
    if ((size_t)out_size >= nl + (size_t)BB * TT) {
        preds = outf;
        logits = outf + BB * TT;
    } else {
        logits = outf;
    }

    control_kernel<<<1, 32>>>(actions);
    tokxw_kernel<<<dim3(NTOK, 4), 192>>>(embed, aW, ab, bW, bb, sW, sb, rW, rb);

    // smem = max(main 21376, chain 26112) floats
    size_t shbytes = 26112u * sizeof(float);
    cudaFuncSetAttribute(main_kernel, cudaFuncAttributeMaxDynamicSharedMemorySize, (int)shbytes);
    main_kernel<<<2 * BB + 2 * NCH, 256, shbytes>>>(aU, bU, sU, rU, sW, sb, rW, rb, Wc, bc);

    dim3 gg((VV + GBN - 1) / GBN, (BB * TT + GBM - 1) / GBM);
    gemm_kernel<<<gg, 256>>>(Wp, bp, logits);
    if (preds) argmax_kernel<<<BB * TT, 256>>>(logits, preds);
}

// round 8
// speedup vs baseline: 2.2331x; 1.2424x over previous
#include <cuda_runtime.h>
#include <math.h>

#define BB 32
#define SS 32
#define TT 31
#define HH 256
#define H3 768
#define VV 12000
#define NTOK 32
#define BOUND 16
#define ATP 1024   // padded row length of g_attT

// ---------------- metadata (written by control kernel) ----------------
__device__ signed char g_la[TT][BB];
__device__ signed char g_npop[TT][BB];
__device__ signed char g_pop_slot[TT][BB][SS];
__device__ signed char g_pop_tok[TT][BB][SS];
__device__ signed char g_spush_slot[TT][BB];   // -1 none
__device__ signed char g_spush_tok[TT][BB];    // -1 = rfinal value, >=0 token
__device__ signed char g_bpush_tok[TT][BB];    // -1 none
__device__ signed char g_stop[TT][BB];         // stack top after step

// precomputed token xw tables: set 0=a,1=b,2=s,3=r
__device__ __align__(16) float g_tokxw[4][NTOK][H3];
// attention outputs TRANSPOSED: [hidden c][row], row = b*TT + t; zero padding
__device__ __align__(16) float g_attT[HH][ATP];
// fused argmax accumulators (reset every launch by control_kernel)
__device__ unsigned long long g_amax[BB * TT];

// ---------------- small asm helpers ----------------
__device__ __forceinline__ unsigned long long pk2(float lo, float hi) {
    unsigned long long r;
    asm("mov.b64 %0, {%1, %2};" : "=l"(r) : "f"(lo), "f"(hi));
    return r;
}
__device__ __forceinline__ void upk2(float& lo, float& hi, unsigned long long v) {
    asm("mov.b64 {%0, %1}, %2;" : "=f"(lo), "=f"(hi) : "l"(v));
}
__device__ __forceinline__ void ffma2(unsigned long long& d, unsigned long long a,
                                      unsigned long long b) {
    asm("fma.rn.f32x2 %0, %1, %2, %3;" : "=l"(d) : "l"(a), "l"(b), "l"(d));
}
__device__ __forceinline__ unsigned smem_u32(const void* p) {
    return (unsigned)__cvta_generic_to_shared(p);
}
__device__ __forceinline__ void st_peer(unsigned addr, unsigned peer, float v) {
    unsigned pa;
    asm volatile("mapa.shared::cluster.u32 %0, %1, %2;" : "=r"(pa) : "r"(addr), "r"(peer));
    asm volatile("st.shared::cluster.f32 [%0], %1;" :: "r"(pa), "f"(v) : "memory");
}
#define CLUSTER_SYNC() do { \
    asm volatile("barrier.cluster.arrive.aligned;" ::: "memory"); \
    asm volatile("barrier.cluster.wait.aligned;" ::: "memory"); } while (0)

#define CP16(dst, src) \
    asm volatile("cp.async.cg.shared.global [%0], [%1], 16;" :: "r"(dst), "l"(src))
#define CP_COMMIT() asm volatile("cp.async.commit_group;" ::: "memory")

__device__ __forceinline__ float sigm(float v) { return 1.f / (1.f + expf(-v)); }

// ---------------- control kernel: pure integer RNNG simulation ----------------
__global__ void control_kernel(const int* __restrict__ actions) {
    int b = threadIdx.x;
    for (int r = b; r < BB * TT; r += 32) g_amax[r] = 0ull;  // reset argmax keys
    int st = -1, tt_ = -1, bt = 0, acc = 1;  // bt=0 after initial buffer push
    signed char tm[SS];
    signed char stok[SS];

    for (int t = 0; t < TT; t++) {
        int a = actions[b * SS + t];
        int la = a * acc;
        int is_red = (la == 2) ? 1 : 0;
        int is_nt  = (la > 2 && la < BOUND) ? 1 : 0;
        int is_gen = (la >= BOUND) ? 1 : 0;

        int np = 0;
        int ir = is_red, aok = 1;
        for (int i = 0; i < SS; i++) {
            if (!(ir && aok)) break;
            int can1 = (st >= 0);
            int pslot = -1;
            if (can1) { pslot = st; st--; }
            aok = aok & can1;
            int tag = 0;
            if (ir && aok) {
                int can2 = (tt_ >= 0);
                if (can2) { tag = tm[tt_]; tt_--; }
                aok = aok & can2;
            }
            int outm = ir & aok;
            if (outm) {
                g_pop_slot[t][b][np] = (signed char)pslot;
                g_pop_tok[t][b][np]  = stok[pslot];
                np++;
            }
            ir = (ir - tag) * aok;
        }
        int racc = aok;
        int sslot = -1, stokv = -2;
        if (is_red && racc) {
            int can = (st + 1 < SS);
            if (can) { st++; sslot = st; stokv = -1; stok[st] = -1; }
            racc &= can;
            if (racc) {
                int can2 = (tt_ + 1 < SS);
                if (can2) { tt_++; tm[tt_] = 0; }
                racc &= can2;
            }
        }
        unsigned ball = __ballot_sync(0xffffffffu, is_red);
        int tot = np;
        for (int o = 16; o > 0; o >>= 1) tot += __shfl_xor_sync(0xffffffffu, tot, o);
        int red_mult = 1;
        if (ball) red_mult = (tot == 0) ? 0 : racc;
        acc *= red_mult;

        if (is_nt) {
            int s5 = (st + 1 < SS);
            if (s5) { st++; stok[st] = (signed char)la; sslot = st; stokv = la; }
            acc *= s5;
            if (s5) {
                int s6 = (tt_ + 1 < SS);
                if (s6) { tt_++; tm[tt_] = 1; }
                acc *= s6;
            }
        }
        int bpush = -1;
        if (is_gen) {
            int s7 = (st + 1 < SS);
            if (s7) { st++; stok[st] = (signed char)la; sslot = st; stokv = la; }
            acc *= s7;
            int s8 = 1;
            if (s7) {
                s8 = (tt_ + 1 < SS);
                if (s8) { tt_++; tm[tt_] = 0; }
                acc *= s8;
            }
            if (s7 && s8) {
                int s9 = (bt + 1 < SS);
                if (s9) { bt++; bpush = la; }
                acc *= s9;
            }
        }
        g_bpush_tok[t][b]  = (signed char)bpush;
        g_la[t][b]         = (signed char)la;
        g_npop[t][b]       = (signed char)np;
        g_spush_slot[t][b] = (signed char)sslot;
        g_spush_tok[t][b]  = (signed char)stokv;
        g_stop[t][b]       = (signed char)st;
    }
}

// ---------------- token xw tables ----------------
__global__ void tokxw_kernel(const float* __restrict__ embed,
                             const float* __restrict__ aW, const float* __restrict__ ab,
                             const float* __restrict__ bW, const float* __restrict__ bb,
                             const float* __restrict__ sW, const float* __restrict__ sb,
                             const float* __restrict__ rW, const float* __restrict__ rb) {
    int tok = blockIdx.x;
    int set = blockIdx.y;
    const float* W  = (set == 0) ? aW : (set == 1) ? bW : (set == 2) ? sW : rW;
    const float* bi = (set == 0) ? ab : (set == 1) ? bb : (set == 2) ? sb : rb;
    int tid = threadIdx.x;  // 192 threads
    const float4* W4 = (const float4*)W;
    float4 acc = __ldg((const float4*)bi + tid);
    const float* x = embed + (size_t)tok * HH;
#pragma unroll 8
    for (int k = 0; k < HH; k++) {
        float xk = __ldg(x + k);
        float4 w = __ldg(W4 + k * 192 + tid);
        acc.x += xk * w.x; acc.y += xk * w.y; acc.z += xk * w.z; acc.w += xk * w.w;
    }
    ((float4*)(&g_tokxw[set][tok][0]))[tid] = acc;
}

// ---------------- half matvec: this CTA's 384 of 768 cols ----------------
__device__ __forceinline__ void mv_half(const float* __restrict__ M, const float* __restrict__ x,
                                        float* out, const float* __restrict__ bias,
                                        int tid, int rank, float* part) {
    __syncthreads();
    int w = tid >> 5, l = tid & 31;
    const float4* M4 = (const float4*)M + (size_t)(w * 32) * 192 + rank * 32;
    const float* xs = x + w * 32;
    float4 a0 = make_float4(0.f, 0.f, 0.f, 0.f), a1 = a0, a2 = a0;
#pragma unroll 2
    for (int k = 0; k < 32; k++) {
        float xk = xs[k];
        const float4* row = M4 + k * 192;
        float4 m0 = __ldg(row + l);
        float4 m1 = __ldg(row + 64 + l);
        float4 m2 = __ldg(row + 128 + l);
        a0.x += xk * m0.x; a0.y += xk * m0.y; a0.z += xk * m0.z; a0.w += xk * m0.w;
        a1.x += xk * m1.x; a1.y += xk * m1.y; a1.z += xk * m1.z; a1.w += xk * m1.w;
        a2.x += xk * m2.x; a2.y += xk * m2.y; a2.z += xk * m2.z; a2.w += xk * m2.w;
    }
    float4* p4 = (float4*)part + w * 96;
    p4[l] = a0; p4[32 + l] = a1; p4[64 + l] = a2;
    __syncthreads();
    if (tid < 128) {
#pragma unroll
        for (int g = 0; g < 3; g++) {
            int c = g * 256 + rank * 128 + tid;
            float s = bias ? __ldg(bias + c) : 0.f;
#pragma unroll
            for (int w2 = 0; w2 < 8; w2++) s += part[w2 * 384 + g * 128 + tid];
            out[c] = s;
        }
    }
}

// half piece matvec: out[tid<128] = (x @ Wpiece)[rank*128 + tid]
__device__ __forceinline__ void piece_half(const float* __restrict__ W, const float* __restrict__ x,
                                           float* out, int tid, int rank, float* part) {
    __syncthreads();
    int w = tid >> 5, l = tid & 31;
    const float4* W4 = (const float4*)W + (size_t)(w * 32) * 64 + rank * 32;
    const float* xs = x + w * 32;
    float4 a = make_float4(0.f, 0.f, 0.f, 0.f);
#pragma unroll 4
    for (int k = 0; k < 32; k++) {
        float xk = xs[k];
        float4 m = __ldg(W4 + k * 64 + l);
        a.x += xk * m.x; a.y += xk * m.y; a.z += xk * m.z; a.w += xk * m.w;
    }
    ((float4*)part)[w * 32 + l] = a;
    __syncthreads();
    if (tid < 128) {
        float s = 0.f;
#pragma unroll
        for (int w2 = 0; w2 < 8; w2++) s += part[w2 * 128 + tid];
        out[tid] = s;
    }
}

// ---------------- main kernel: 2-CTA cluster per batch lane (round-5) ----------------
extern __shared__ float smem_f[];
__global__ __launch_bounds__(256) __cluster_dims__(2, 1, 1)
void main_kernel(
    const float* __restrict__ aU, const float* __restrict__ bU,
    const float* __restrict__ sU, const float* __restrict__ rU,
    const float* __restrict__ sW, const float* __restrict__ sb,
    const float* __restrict__ rW, const float* __restrict__ rb,
    const float* __restrict__ Wc, const float* __restrict__ bc) {
    int tid = threadIdx.x;
    int b = blockIdx.x >> 1;
    int rank = blockIdx.x & 1;
    unsigned peer = (unsigned)(rank ^ 1);

    float* sm_v = smem_f;            // [32][256]
    float* hs   = sm_v + SS * HH;    // [32][256]
    float* bufh = hs + SS * HH;      // [256]
    float* ah   = bufh + HH;         // [256]
    float* hred = ah + HH;           // [256]
    float* s_hu = hred + HH;         // [768]
    float* s_xw = s_hu + H3;         // [768]
    float* part = s_xw + H3;         // [8*384]
    float* p_s  = part + 8 * 384;    // [128]
    float* p_ah = p_s + 128;         // [128]
    float* p_b  = p_ah + 128;        // [128]

    unsigned base_u32 = smem_u32(smem_f);
    unsigned hs_a   = base_u32 + (unsigned)((char*)hs - (char*)smem_f);
    unsigned bufh_a = base_u32 + (unsigned)((char*)bufh - (char*)smem_f);
    unsigned ah_a   = base_u32 + (unsigned)((char*)ah - (char*)smem_f);
    unsigned hred_a = base_u32 + (unsigned)((char*)hred - (char*)smem_f);

    // initial buffer push: bufh = GRU_b(embed[1], h=0)
    {
        const float* xw = &g_tokxw[1][1][0];
        bufh[tid] = sigm(xw[tid]) * tanhf(xw[2 * HH + tid]);
        if (tid < 128) p_s[tid] = 0.f;
    }
    __syncthreads();

    int prev_stop = -1;

    for (int t = 0; t < TT; t++) {
        int la    = g_la[t][b];
        int np    = g_npop[t][b];
        int sslot = g_spush_slot[t][b];
        int stokv = g_spush_tok[t][b];
        int bpush = g_bpush_tok[t][b];
        int stop  = g_stop[t][b];

        // ---- reduce chain ----
        for (int i = 0; i < np; i++) {
            int slot = g_pop_slot[t][b][i];
            int tok  = g_pop_tok[t][b][i];
            if (tok >= 0 && i == 0) {
                const float* xw = &g_tokxw[3][tok][0];
                __syncthreads();
                hred[tid] = sigm(xw[tid]) * tanhf(xw[2 * HH + tid]);
                __syncthreads();
            } else {
                const float* xw;
                if (tok >= 0) xw = &g_tokxw[3][tok][0];
                else { mv_half(rW, &sm_v[slot * HH], s_xw, rb, tid, rank, part); xw = s_xw; }
                if (i > 0) mv_half(rU, hred, s_hu, nullptr, tid, rank, part);
                if (tid < 128) {
                    int c = rank * 128 + tid;
                    float hz = 0.f, hr = 0.f, hn = 0.f, hp = 0.f;
                    if (i > 0) { hz = s_hu[c]; hr = s_hu[HH + c]; hn = s_hu[2 * HH + c]; hp = hred[c]; }
                    float z = sigm(xw[c] + hz);
                    float r = sigm(xw[HH + c] + hr);
                    float n = tanhf(xw[2 * HH + c] + r * hn);
                    float h = (1.f - z) * hp + z * n;
                    hred[c] = h;
                    st_peer(hred_a + (unsigned)c * 4, peer, h);
                }
                CLUSTER_SYNC();
            }
        }

        // ---- stack push ----
        if (sslot >= 0) {
            const float* xw_s;
            if (stokv >= 0) {
                xw_s = &g_tokxw[2][stokv][0];
            } else {
                __syncthreads();
                sm_v[sslot * HH + tid] = hred[tid];
                mv_half(sW, hred, s_xw, sb, tid, rank, part);
                xw_s = s_xw;
            }
            if (sslot > 0) mv_half(sU, &hs[(sslot - 1) * HH], s_hu, nullptr, tid, rank, part);
            if (tid < 128) {
                int c = rank * 128 + tid;
                float hz = 0.f, hr = 0.f, hn = 0.f, hp = 0.f;
                if (sslot > 0) {
                    hz = s_hu[c]; hr = s_hu[HH + c]; hn = s_hu[2 * HH + c];
                    hp = hs[(sslot - 1) * HH + c];
                }
                float z = sigm(xw_s[c] + hz);
                float r = sigm(xw_s[HH + c] + hr);
                float n = tanhf(xw_s[2 * HH + c] + r * hn);
                float h = (1.f - z) * hp + z * n;
                hs[sslot * HH + c] = h;
                st_peer(hs_a + (unsigned)(sslot * HH + c) * 4, peer, h);
            }
        }

        // ---- buffer push (GEN) ----
        if (bpush >= 0) {
            mv_half(bU, bufh, s_hu, nullptr, tid, rank, part);
            if (tid < 128) {
                int c = rank * 128 + tid;
                const float* xw = &g_tokxw[1][bpush][0];
                float z = sigm(xw[c] + s_hu[c]);
                float r = sigm(xw[HH + c] + s_hu[HH + c]);
                float n = tanhf(xw[2 * HH + c] + r * s_hu[2 * HH + c]);
                float h = (1.f - z) * bufh[c] + z * n;
                bufh[c] = h;
                st_peer(bufh_a + (unsigned)c * 4, peer, h);
            }
        }

        // ---- action GRU ----
        if (t > 0) {
            mv_half(aU, ah, s_hu, nullptr, tid, rank, part);
            if (tid < 128) {
                int c = rank * 128 + tid;
                const float* xw = &g_tokxw[0][la][0];
                float z = sigm(xw[c] + s_hu[c]);
                float r = sigm(xw[HH + c] + s_hu[HH + c]);
                float n = tanhf(xw[2 * HH + c] + r * s_hu[2 * HH + c]);
                float h = (1.f - z) * ah[c] + z * n;
                ah[c] = h;
                st_peer(ah_a + (unsigned)c * 4, peer, h);
            }
        } else {
            __syncthreads();
            const float* xw = &g_tokxw[0][la][0];
            ah[tid] = sigm(xw[tid]) * tanhf(xw[2 * HH + tid]);
        }
        CLUSTER_SYNC();   // all state halves exchanged

        // ---- attention with dirty-tracked [256,256] pieces of Wc ----
        {
            bool s_dirty = (stop != prev_stop) || (sslot >= 0);
            if (s_dirty) {
                if (stop < 0) {
                    __syncthreads();
                    if (tid < 128) p_s[tid] = 0.f;
                } else {
                    piece_half(Wc, &hs[stop * HH], p_s, tid, rank, part);
                }
            }
            piece_half(Wc + (size_t)HH * HH, ah, p_ah, tid, rank, part);
            if (t == 0 || bpush >= 0)
                piece_half(Wc + (size_t)2 * HH * HH, bufh, p_b, tid, rank, part);
            if (tid < 128) {
                int c = rank * 128 + tid;
                float v = p_s[tid] + p_ah[tid] + p_b[tid] + __ldg(bc + c);
                g_attT[c][b * TT + t] = tanhf(v);
            }
            prev_stop = stop;
        }
        CLUSTER_SYNC();   // protect state reads from next step's peer writes
    }
}

// ---------------- logits GEMM + fused argmax ----------------
#define GBM 128
#define GBN 128
#define GBK 32
extern __shared__ float gsm[];
__global__ __launch_bounds__(256, 2) void gemm_kernel(const float* __restrict__ Wp,
                                                      const float* __restrict__ bp,
                                                      float* __restrict__ out) {
    float* As = gsm;                     // [2][GBK][GBM] 32KB
    float* Bs = gsm + 2 * GBK * GBM;     // [2][GBK][GBN] 32KB
    int tid = threadIdx.x;
    int c0 = blockIdx.x * GBN;
    int row0 = blockIdx.y * GBM;
    const int MROWS = BB * TT;
    const float* attT = &g_attT[0][0];

    unsigned sA = smem_u32(As);
    unsigned sB = smem_u32(Bs);

    int ty = tid >> 4, tx = tid & 15;

    unsigned long long accp[8][4];
#pragma unroll
    for (int i = 0; i < 8; i++)
#pragma unroll
        for (int j = 0; j < 4; j++) accp[i][j] = 0ull;

    const int NTILE = HH / GBK;   // 8

#define ISSUE_TILE(buf, kk) do {                                              \
        _Pragma("unroll")                                                     \
        for (int i_ = 0; i_ < 4; i_++) {                                      \
            int idx_ = tid * 4 + i_;                                          \
            int k_ = idx_ >> 5;                                               \
            int q_ = idx_ & 31;                                               \
            unsigned da_ = sA + (unsigned)((((buf) * GBK + k_) * GBM + q_ * 4) * 4); \
            CP16(da_, attT + (size_t)((kk) + k_) * ATP + row0 + q_ * 4);      \
            int gc_ = c0 + q_ * 4;                                            \
            if (gc_ + 3 < VV) {                                               \
                unsigned db_ = sB + (unsigned)((((buf) * GBK + k_) * GBN + q_ * 4) * 4); \
                CP16(db_, Wp + (size_t)((kk) + k_) * VV + gc_);               \
            } else {                                                          \
                *(float4*)&Bs[((buf) * GBK + k_) * GBN + q_ * 4] =            \
                    make_float4(0.f, 0.f, 0.f, 0.f);                          \
            }                                                                 \
        }                                                                     \
        CP_COMMIT();                                                          \
    } while (0)

    ISSUE_TILE(0, 0);
    for (int tIdx = 0; tIdx < NTILE; tIdx++) {
        int buf = tIdx & 1;
        if (tIdx + 1 < NTILE) {
            ISSUE_TILE((tIdx + 1) & 1, (tIdx + 1) * GBK);
            asm volatile("cp.async.wait_group 1;" ::: "memory");
        } else {
            asm volatile("cp.async.wait_group 0;" ::: "memory");
        }
        __syncthreads();
#pragma unroll 8
        for (int k = 0; k < GBK; k++) {
            const float* arow = &As[(buf * GBK + k) * GBM + ty * 8];
            float4 a01 = *(const float4*)arow;
            float4 a23 = *(const float4*)(arow + 4);
            const ulonglong2* brow = (const ulonglong2*)&Bs[(buf * GBK + k) * GBN + tx * 8];
            ulonglong2 b01 = brow[0];
            ulonglong2 b23 = brow[1];
            unsigned long long brp[4] = {b01.x, b01.y, b23.x, b23.y};
            float ar[8] = {a01.x, a01.y, a01.z, a01.w, a23.x, a23.y, a23.z, a23.w};
#pragma unroll
            for (int i = 0; i < 8; i++) {
                unsigned long long ap = pk2(ar[i], ar[i]);
                ffma2(accp[i][0], ap, brp[0]);
                ffma2(accp[i][1], ap, brp[1]);
                ffma2(accp[i][2], ap, brp[2]);
                ffma2(accp[i][3], ap, brp[3]);
            }
        }
        __syncthreads();
    }

    float bias[8];
#pragma unroll
    for (int j = 0; j < 8; j++) {
        int gc = c0 + tx * 8 + j;
        bias[j] = (gc < VV) ? __ldg(bp + gc) : 0.f;
    }
#pragma unroll
    for (int i = 0; i < 8; i++) {
        int grow = row0 + ty * 8 + i;
        if (grow >= MROWS) continue;
        int gc = c0 + tx * 8;
        float acc[8];
#pragma unroll
        for (int j = 0; j < 4; j++) upk2(acc[2 * j], acc[2 * j + 1], accp[i][j]);
#pragma unroll
        for (int j = 0; j < 8; j++) acc[j] += bias[j];
        // store logits
        if (gc + 7 < VV) {
            float4 o0 = make_float4(acc[0], acc[1], acc[2], acc[3]);
            float4 o1 = make_float4(acc[4], acc[5], acc[6], acc[7]);
            *((float4*)(out + (size_t)grow * VV + gc)) = o0;
            *((float4*)(out + (size_t)grow * VV + gc + 4)) = o1;
        } else {
#pragma unroll
            for (int j = 0; j < 8; j++)
                if (gc + j < VV) out[(size_t)grow * VV + gc + j] = acc[j];
        }
        // fused argmax: local 8-col reduce
        float rbest = -3.4e38f;
        int rbi = 0;
#pragma unroll
        for (int j = 0; j < 8; j++) {
            int gcj = gc + j;
            float v = (gcj < VV) ? acc[j] : -3.4e38f;
            if (v > rbest) { rbest = v; rbi = gcj; }
        }
        // half-warp (16 lanes of same row) shfl reduce
#pragma unroll
        for (int o = 8; o > 0; o >>= 1) {
            float ov = __shfl_xor_sync(0xffffffffu, rbest, o);
            int oi = __shfl_xor_sync(0xffffffffu, rbi, o);
            if (ov > rbest || (ov == rbest && oi < rbi)) { rbest = ov; rbi = oi; }
        }
        if (tx == 0) {
            unsigned u = __float_as_uint(rbest);
            unsigned m = (u & 0x80000000u) ? ~u : (u | 0x80000000u);
            unsigned long long key =
                ((unsigned long long)m << 32) | (unsigned long long)(0xFFFFFFFFu - (unsigned)rbi);
            atomicMax(&g_amax[grow], key);
        }
    }
}

// ---------------- decode preds from argmax keys ----------------
__global__ void preds_kernel(float* __restrict__ preds) {
    int r = blockIdx.x * 256 + threadIdx.x;
    if (r < BB * TT) {
        unsigned long long k = g_amax[r];
        preds[r] = (float)(0xFFFFFFFFu - (unsigned)(k & 0xFFFFFFFFull));
    }
}

// ---------------- launch ----------------
extern "C" void kernel_launch(void* const* d_in, const int* in_sizes, int n_in,
                              void* d_out, int out_size) {
    const int*   actions = (const int*)d_in[0];
    const float* embed = (const float*)d_in[1];
    const float* aW = (const float*)d_in[2];
    const float* aU = (const float*)d_in[3];
    const float* ab = (const float*)d_in[4];
    const float* bW = (const float*)d_in[5];
    const float* bU = (const float*)d_in[6];
    const float* bb = (const float*)d_in[7];
    const float* sW = (const float*)d_in[8];
    const float* sU = (const float*)d_in[9];
    const float* sb = (const float*)d_in[10];
    const float* rW = (const float*)d_in[11];
    const float* rU = (const float*)d_in[12];
    const float* rb = (const float*)d_in[13];
    const float* Wc = (const float*)d_in[14];
    const float* bc = (const float*)d_in[15];
    const float* Wp = (const float*)d_in[16];
    const float* bp = (const float*)d_in[17];

    float* outf = (float*)d_out;
    size_t nl = (size_t)BB * TT * VV;
    float* preds = nullptr;
    float* logits;
    if ((size_t)out_size >= nl + (size_t)BB * TT) {
        preds = outf;
        logits = outf + BB * TT;
    } else {
        logits = outf;
    }

    control_kernel<<<1, 32>>>(actions);
    tokxw_kernel<<<dim3(NTOK, 4), 192>>>(embed, aW, ab, bW, bb, sW, sb, rW, rb);

    // main smem: sm_v + hs + bufh/ah/hred + s_hu/s_xw + part(8*384) + p_s/p_ah/p_b
    size_t shfloats = (size_t)SS * HH * 2 + HH * 3 + H3 * 2 + 8 * 384 + 3 * 128;
    size_t shbytes = shfloats * sizeof(float);
    cudaFuncSetAttribute(main_kernel, cudaFuncAttributeMaxDynamicSharedMemorySize, (int)shbytes);
    main_kernel<<<2 * BB, 256, shbytes>>>(aU, bU, sU, rU, sW, sb, rW, rb, Wc, bc);

    size_t gemm_sh = (size_t)4 * GBK * GBM * sizeof(float);  // 64 KB
    cudaFuncSetAttribute(gemm_kernel, cudaFuncAttributeMaxDynamicSharedMemorySize, (int)gemm_sh);
    dim3 gg((VV + GBN - 1) / GBN, (BB * TT + GBM - 1) / GBM);
    gemm_kernel<<<gg, 256, gemm_sh>>>(Wp, bp, logits);
    if (preds) preds_kernel<<<(BB * TT + 255) / 256, 256>>>(preds);
}

// round 9
// speedup vs baseline: 2.3928x; 1.0715x over previous
#include <cuda_runtime.h>
#include <math.h>

#define BB 32
#define SS 32
#define TT 31
#define HH 256
#define H3 768
#define VV 12000
#define NTOK 32
#define BOUND 16
#define ATP 1024   // padded row length of g_attT
#define NPAIR 16   // lane pairs
#define CL 4       // CTAs per cluster (quarter-column split)

// ---------------- metadata (written by control kernel) ----------------
__device__ signed char g_la[TT][BB];
__device__ signed char g_npop[TT][BB];
__device__ signed char g_pop_slot[TT][BB][SS];
__device__ signed char g_pop_tok[TT][BB][SS];
__device__ signed char g_spush_slot[TT][BB];   // -1 none
__device__ signed char g_spush_tok[TT][BB];    // -1 = rfinal value, >=0 token
__device__ signed char g_bpush_tok[TT][BB];    // -1 none
__device__ signed char g_stop[TT][BB];         // stack top after step

// precomputed token xw tables: set 0=a,1=b,2=s,3=r
__device__ __align__(16) float g_tokxw[4][NTOK][H3];
// attention outputs TRANSPOSED: [hidden c][row]; rows >= BB*TT stay zero
__device__ __align__(16) float g_attT[HH][ATP];
// fused argmax accumulators (reset every launch by control_kernel)
__device__ unsigned long long g_amax[BB * TT];

// ---------------- small asm helpers ----------------
__device__ __forceinline__ unsigned long long pk2(float lo, float hi) {
    unsigned long long r;
    asm("mov.b64 %0, {%1, %2};" : "=l"(r) : "f"(lo), "f"(hi));
    return r;
}
__device__ __forceinline__ void upk2(float& lo, float& hi, unsigned long long v) {
    asm("mov.b64 {%0, %1}, %2;" : "=f"(lo), "=f"(hi) : "l"(v));
}
__device__ __forceinline__ void ffma2(unsigned long long& d, unsigned long long a,
                                      unsigned long long b) {
    asm("fma.rn.f32x2 %0, %1, %2, %3;" : "=l"(d) : "l"(a), "l"(b), "l"(d));
}
__device__ __forceinline__ unsigned smem_u32(const void* p) {
    return (unsigned)__cvta_generic_to_shared(p);
}
__device__ __forceinline__ void st_peer(unsigned addr, unsigned peer, float v) {
    unsigned pa;
    asm volatile("mapa.shared::cluster.u32 %0, %1, %2;" : "=r"(pa) : "r"(addr), "r"(peer));
    asm volatile("st.shared::cluster.f32 [%0], %1;" :: "r"(pa), "f"(v) : "memory");
}
__device__ __forceinline__ void st_peer3(unsigned addr, int rank, float v) {
    st_peer(addr, (unsigned)((rank + 1) & 3), v);
    st_peer(addr, (unsigned)((rank + 2) & 3), v);
    st_peer(addr, (unsigned)((rank + 3) & 3), v);
}
#define CLUSTER_SYNC() do { \
    asm volatile("barrier.cluster.arrive.aligned;" ::: "memory"); \
    asm volatile("barrier.cluster.wait.aligned;" ::: "memory"); } while (0)

#define CP16(dst, src) \
    asm volatile("cp.async.cg.shared.global [%0], [%1], 16;" :: "r"(dst), "l"(src))
#define CP_COMMIT() asm volatile("cp.async.commit_group;" ::: "memory")

__device__ __forceinline__ float sigm(float v) { return 1.f / (1.f + expf(-v)); }

// ---------------- control kernel: pure integer RNNG simulation ----------------
__global__ void control_kernel(const int* __restrict__ actions) {
    int b = threadIdx.x;
    for (int r = b; r < BB * TT; r += 32) g_amax[r] = 0ull;
    int st = -1, tt_ = -1, bt = 0, acc = 1;
    signed char tm[SS];
    signed char stok[SS];

    for (int t = 0; t < TT; t++) {
        int a = actions[b * SS + t];
        int la = a * acc;
        int is_red = (la == 2) ? 1 : 0;
        int is_nt  = (la > 2 && la < BOUND) ? 1 : 0;
        int is_gen = (la >= BOUND) ? 1 : 0;

        int np = 0;
        int ir = is_red, aok = 1;
        for (int i = 0; i < SS; i++) {
            if (!(ir && aok)) break;
            int can1 = (st >= 0);
            int pslot = -1;
            if (can1) { pslot = st; st--; }
            aok = aok & can1;
            int tag = 0;
            if (ir && aok) {
                int can2 = (tt_ >= 0);
                if (can2) { tag = tm[tt_]; tt_--; }
                aok = aok & can2;
            }
            int outm = ir & aok;
            if (outm) {
                g_pop_slot[t][b][np] = (signed char)pslot;
                g_pop_tok[t][b][np]  = stok[pslot];
                np++;
            }
            ir = (ir - tag) * aok;
        }
        int racc = aok;
        int sslot = -1, stokv = -2;
        if (is_red && racc) {
            int can = (st + 1 < SS);
            if (can) { st++; sslot = st; stokv = -1; stok[st] = -1; }
            racc &= can;
            if (racc) {
                int can2 = (tt_ + 1 < SS);
                if (can2) { tt_++; tm[tt_] = 0; }
                racc &= can2;
            }
        }
        unsigned ball = __ballot_sync(0xffffffffu, is_red);
        int tot = np;
        for (int o = 16; o > 0; o >>= 1) tot += __shfl_xor_sync(0xffffffffu, tot, o);
        int red_mult = 1;
        if (ball) red_mult = (tot == 0) ? 0 : racc;
        acc *= red_mult;

        if (is_nt) {
            int s5 = (st + 1 < SS);
            if (s5) { st++; stok[st] = (signed char)la; sslot = st; stokv = la; }
            acc *= s5;
            if (s5) {
                int s6 = (tt_ + 1 < SS);
                if (s6) { tt_++; tm[tt_] = 1; }
                acc *= s6;
            }
        }
        int bpush = -1;
        if (is_gen) {
            int s7 = (st + 1 < SS);
            if (s7) { st++; stok[st] = (signed char)la; sslot = st; stokv = la; }
            acc *= s7;
            int s8 = 1;
            if (s7) {
                s8 = (tt_ + 1 < SS);
                if (s8) { tt_++; tm[tt_] = 0; }
                acc *= s8;
            }
            if (s7 && s8) {
                int s9 = (bt + 1 < SS);
                if (s9) { bt++; bpush = la; }
                acc *= s9;
            }
        }
        g_bpush_tok[t][b]  = (signed char)bpush;
        g_la[t][b]         = (signed char)la;
        g_npop[t][b]       = (signed char)np;
        g_spush_slot[t][b] = (signed char)sslot;
        g_spush_tok[t][b]  = (signed char)stokv;
        g_stop[t][b]       = (signed char)st;
    }
}

// ---------------- token xw tables ----------------
__global__ void tokxw_kernel(const float* __restrict__ embed,
                             const float* __restrict__ aW, const float* __restrict__ ab,
                             const float* __restrict__ bW, const float* __restrict__ bb,
                             const float* __restrict__ sW, const float* __restrict__ sb,
                             const float* __restrict__ rW, const float* __restrict__ rb) {
    int tok = blockIdx.x;
    int set = blockIdx.y;
    const float* W  = (set == 0) ? aW : (set == 1) ? bW : (set == 2) ? sW : rW;
    const float* bi = (set == 0) ? ab : (set == 1) ? bb : (set == 2) ? sb : rb;
    int tid = threadIdx.x;  // 192 threads
    const float4* W4 = (const float4*)W;
    float4 acc = __ldg((const float4*)bi + tid);
    const float* x = embed + (size_t)tok * HH;
#pragma unroll 8
    for (int k = 0; k < HH; k++) {
        float xk = __ldg(x + k);
        float4 w = __ldg(W4 + k * 192 + tid);
        acc.x += xk * w.x; acc.y += xk * w.y; acc.z += xk * w.z; acc.w += xk * w.w;
    }
    ((float4*)(&g_tokxw[set][tok][0]))[tid] = acc;
}

// ---------------- quarter matvec for a LANE PAIR ----------------
// M [256,768] row-major. This CTA owns, per gate g, float4 cols [g*64+rank*16, +16).
// Streams M once, accumulates for both lanes. out_j gets valid values at owned cols.
__device__ __forceinline__ void mvq_pair(const float* __restrict__ M,
                                         const float* __restrict__ x0,
                                         const float* __restrict__ x1,
                                         float* out0, float* out1,
                                         const float* __restrict__ bias,
                                         int tid, int rank,
                                         float* part0, float* part1) {
    __syncthreads();   // protect part + order prior writes to x
    int w = tid >> 5, l = tid & 31;
    const float* xs0 = x0 + w * 32;
    const float* xs1 = x1 + w * 32;
    const float4* Mrow = (const float4*)M + (size_t)(w * 32) * 192;
    int col0 = (l >> 4) * 64 + rank * 16 + (l & 15);     // f4 idx 0..47 -> first 32
    int col1 = 128 + rank * 16 + l;                      // gate2, only l<16
    float4 a0 = make_float4(0.f, 0.f, 0.f, 0.f), b0 = a0, a1 = a0, b1 = a0;
#pragma unroll 4
    for (int k = 0; k < 32; k++) {
        float x0k = xs0[k], x1k = xs1[k];
        float4 m0 = __ldg(Mrow + k * 192 + col0);
        a0.x += x0k * m0.x; a0.y += x0k * m0.y; a0.z += x0k * m0.z; a0.w += x0k * m0.w;
        b0.x += x1k * m0.x; b0.y += x1k * m0.y; b0.z += x1k * m0.z; b0.w += x1k * m0.w;
        if (l < 16) {
            float4 m1 = __ldg(Mrow + k * 192 + col1);
            a1.x += x0k * m1.x; a1.y += x0k * m1.y; a1.z += x0k * m1.z; a1.w += x0k * m1.w;
            b1.x += x1k * m1.x; b1.y += x1k * m1.y; b1.z += x1k * m1.z; b1.w += x1k * m1.w;
        }
    }
    float4* p40 = (float4*)part0 + w * 48;
    float4* p41 = (float4*)part1 + w * 48;
    p40[l] = a0; p41[l] = b0;
    if (l < 16) { p40[32 + l] = a1; p41[32 + l] = b1; }
    __syncthreads();
    if (tid < 192) {
        float s0 = 0.f, s1 = 0.f;
#pragma unroll
        for (int w2 = 0; w2 < 8; w2++) { s0 += part0[w2 * 192 + tid]; s1 += part1[w2 * 192 + tid]; }
        int f4i = tid >> 2;
        int g = f4i >> 4, o = f4i & 15;
        int gc = g * 256 + rank * 64 + o * 4 + (tid & 3);
        if (bias) { float bv = __ldg(bias + gc); s0 += bv; s1 += bv; }
        out0[gc] = s0; out1[gc] = s1;
    }
    // consumers (tid<64 gate section) rely on the next mv's leading sync or
    // explicit __syncthreads at call sites below.
}

// quarter attention piece for a lane pair: out_j[0..63] = (x_j @ Wp)[rank*64 .. +64)
__device__ __forceinline__ void pieceq_pair(const float* __restrict__ Wp,
                                            const float* __restrict__ x0,
                                            const float* __restrict__ x1,
                                            float* out0, float* out1,
                                            bool act0, bool act1,
                                            int tid, int rank,
                                            float* part0, float* part1) {
    __syncthreads();
    int w = tid >> 5, l = tid & 31;
    if (l < 16) {
        const float* xs0 = x0 + w * 32;
        const float* xs1 = x1 + w * 32;
        const float4* W4 = (const float4*)Wp + (size_t)(w * 32) * 64 + rank * 16 + l;
        float4 a = make_float4(0.f, 0.f, 0.f, 0.f), b = a;
#pragma unroll 4
        for (int k = 0; k < 32; k++) {
            float4 m = __ldg(W4 + k * 64);
            float x0k = xs0[k], x1k = xs1[k];
            a.x += x0k * m.x; a.y += x0k * m.y; a.z += x0k * m.z; a.w += x0k * m.w;
            b.x += x1k * m.x; b.y += x1k * m.y; b.z += x1k * m.z; b.w += x1k * m.w;
        }
        ((float4*)part0)[w * 16 + l] = a;
        ((float4*)part1)[w * 16 + l] = b;
    }
    __syncthreads();
    if (tid < 64) {
        float s0 = 0.f, s1 = 0.f;
#pragma unroll
        for (int w2 = 0; w2 < 8; w2++) { s0 += part0[w2 * 64 + tid]; s1 += part1[w2 * 64 + tid]; }
        if (act0) out0[tid] = s0;
        if (act1) out1[tid] = s1;
    }
}

// ---------------- main kernel: 2 lanes per 4-CTA cluster ----------------
extern __shared__ float smem_f[];
__global__ __launch_bounds__(256) __cluster_dims__(CL, 1, 1)
void main_kernel(
    const float* __restrict__ aU, const float* __restrict__ bU,
    const float* __restrict__ sU, const float* __restrict__ rU,
    const float* __restrict__ sW, const float* __restrict__ sb,
    const float* __restrict__ rW, const float* __restrict__ rb,
    const float* __restrict__ Wc, const float* __restrict__ bc) {
    int tid = threadIdx.x;
    int p = blockIdx.x >> 2;
    int rank = blockIdx.x & 3;
    int b0 = p, b1 = p + NPAIR;

    // smem layout (floats)
    float* sm_v0 = smem_f;               // 8192
    float* sm_v1 = sm_v0 + 8192;
    float* hs0   = sm_v1 + 8192;         // 8192
    float* hs1   = hs0 + 8192;
    float* bufh0 = hs1 + 8192;           // 256 each below
    float* bufh1 = bufh0 + 256;
    float* ah0   = bufh1 + 256;
    float* ah1   = ah0 + 256;
    float* hred0 = ah1 + 256;
    float* hred1 = hred0 + 256;
    float* s_hu0 = hred1 + 256;          // 768
    float* s_hu1 = s_hu0 + 768;
    float* s_xw0 = s_hu1 + 768;
    float* s_xw1 = s_xw0 + 768;
    float* part0 = s_xw1 + 768;          // 1536
    float* part1 = part0 + 1536;
    float* p_s0  = part1 + 1536;         // 64 each
    float* p_s1  = p_s0 + 64;
    float* p_ah0 = p_s1 + 64;
    float* p_ah1 = p_ah0 + 64;
    float* p_b0  = p_ah1 + 64;
    float* p_b1  = p_b0 + 64;

    unsigned base_u32 = smem_u32(smem_f);
    unsigned hred_a[2], hs_a[2], bufh_a[2], ah_a[2];
    hred_a[0] = base_u32 + (unsigned)((char*)hred0 - (char*)smem_f);
    hred_a[1] = base_u32 + (unsigned)((char*)hred1 - (char*)smem_f);
    hs_a[0]   = base_u32 + (unsigned)((char*)hs0 - (char*)smem_f);
    hs_a[1]   = base_u32 + (unsigned)((char*)hs1 - (char*)smem_f);
    bufh_a[0] = base_u32 + (unsigned)((char*)bufh0 - (char*)smem_f);
    bufh_a[1] = base_u32 + (unsigned)((char*)bufh1 - (char*)smem_f);
    ah_a[0]   = base_u32 + (unsigned)((char*)ah0 - (char*)smem_f);
    ah_a[1]   = base_u32 + (unsigned)((char*)ah1 - (char*)smem_f);

    float* SMV[2]  = {sm_v0, sm_v1};
    float* HS[2]   = {hs0, hs1};
    float* BUFH[2] = {bufh0, bufh1};
    float* AH[2]   = {ah0, ah1};
    float* HRED[2] = {hred0, hred1};
    float* SHU[2]  = {s_hu0, s_hu1};
    float* SXW[2]  = {s_xw0, s_xw1};
    float* PS[2]   = {p_s0, p_s1};
    float* PAH[2]  = {p_ah0, p_ah1};
    float* PB[2]   = {p_b0, p_b1};
    int BL[2] = {b0, b1};

    // init: bufh = GRU_b(embed[1], 0) full-local, both lanes; p_s zero
    {
        const float* xw = &g_tokxw[1][1][0];
        float v = sigm(xw[tid]) * tanhf(xw[2 * HH + tid]);
        bufh0[tid] = v; bufh1[tid] = v;
        if (tid < 64) { p_s0[tid] = 0.f; p_s1[tid] = 0.f; }
    }
    __syncthreads();

    int prev_stop[2] = {-1, -1};

    for (int t = 0; t < TT; t++) {
        int la_[2], np_[2], sslot_[2], stokv_[2], bpush_[2], stop_[2];
#pragma unroll
        for (int j = 0; j < 2; j++) {
            int bl = BL[j];
            la_[j]    = g_la[t][bl];
            np_[j]    = g_npop[t][bl];
            sslot_[j] = g_spush_slot[t][bl];
            stokv_[j] = g_spush_tok[t][bl];
            bpush_[j] = g_bpush_tok[t][bl];
            stop_[j]  = g_stop[t][bl];
        }
        int npmax = np_[0] > np_[1] ? np_[0] : np_[1];

        // ---- reduce chain (shared weight streams, per-lane gates) ----
        for (int i = 0; i < npmax; i++) {
            bool act[2], needW[2];
            int tok[2], slot[2];
#pragma unroll
            for (int j = 0; j < 2; j++) {
                act[j] = (i < np_[j]);
                tok[j] = act[j] ? (int)g_pop_tok[t][BL[j]][i] : 0;
                slot[j] = act[j] ? (int)g_pop_slot[t][BL[j]][i] : 0;
                needW[j] = act[j] && tok[j] < 0;
            }
            if (needW[0] || needW[1])
                mvq_pair(rW, needW[0] ? &SMV[0][slot[0] * HH] : HRED[0],
                             needW[1] ? &SMV[1][slot[1] * HH] : HRED[1],
                         SXW[0], SXW[1], rb, tid, rank, part0, part1);
            if (i > 0)
                mvq_pair(rU, HRED[0], HRED[1], SHU[0], SHU[1], nullptr,
                         tid, rank, part0, part1);
            __syncthreads();
            if (tid < 64) {
                int ch = rank * 64 + tid;
#pragma unroll
                for (int j = 0; j < 2; j++) {
                    if (!act[j]) continue;
                    const float* xw = (tok[j] >= 0) ? &g_tokxw[3][tok[j]][0] : SXW[j];
                    float hz = 0.f, hr = 0.f, hn = 0.f, hp = 0.f;
                    if (i > 0) {
                        hz = SHU[j][ch]; hr = SHU[j][HH + ch]; hn = SHU[j][2 * HH + ch];
                        hp = HRED[j][ch];
                    }
                    float z = sigm(xw[ch] + hz);
                    float r = sigm(xw[HH + ch] + hr);
                    float n = tanhf(xw[2 * HH + ch] + r * hn);
                    float h = (1.f - z) * hp + z * n;
                    HRED[j][ch] = h;
                    st_peer3(hred_a[j] + (unsigned)ch * 4, rank, h);
                }
            }
            CLUSTER_SYNC();
        }

        // ---- stack push ----
        {
            bool red[2] = {sslot_[0] >= 0 && stokv_[0] == -1,
                           sslot_[1] >= 0 && stokv_[1] == -1};
            if (red[0]) SMV[0][sslot_[0] * HH + tid] = HRED[0][tid];
            if (red[1]) SMV[1][sslot_[1] * HH + tid] = HRED[1][tid];
            if (red[0] || red[1])
                mvq_pair(sW, HRED[0], HRED[1], SXW[0], SXW[1], sb, tid, rank, part0, part1);
            bool pu[2] = {sslot_[0] > 0, sslot_[1] > 0};
            if (pu[0] || pu[1])
                mvq_pair(sU, pu[0] ? &HS[0][(sslot_[0] - 1) * HH] : HRED[0],
                             pu[1] ? &HS[1][(sslot_[1] - 1) * HH] : HRED[1],
                         SHU[0], SHU[1], nullptr, tid, rank, part0, part1);
            __syncthreads();
            if (tid < 64) {
                int ch = rank * 64 + tid;
#pragma unroll
                for (int j = 0; j < 2; j++) {
                    if (sslot_[j] < 0) continue;
                    const float* xw = (stokv_[j] >= 0) ? &g_tokxw[2][stokv_[j]][0] : SXW[j];
                    float hz = 0.f, hr = 0.f, hn = 0.f, hp = 0.f;
                    if (sslot_[j] > 0) {
                        hz = SHU[j][ch]; hr = SHU[j][HH + ch]; hn = SHU[j][2 * HH + ch];
                        hp = HS[j][(sslot_[j] - 1) * HH + ch];
                    }
                    float z = sigm(xw[ch] + hz);
                    float r = sigm(xw[HH + ch] + hr);
                    float n = tanhf(xw[2 * HH + ch] + r * hn);
                    float h = (1.f - z) * hp + z * n;
                    HS[j][sslot_[j] * HH + ch] = h;
                    st_peer3(hs_a[j] + (unsigned)(sslot_[j] * HH + ch) * 4, rank, h);
                }
            }
        }

        // ---- buffer push (GEN) ----
        {
            bool gp[2] = {bpush_[0] >= 0, bpush_[1] >= 0};
            if (gp[0] || gp[1]) {
                mvq_pair(bU, BUFH[0], BUFH[1], SHU[0], SHU[1], nullptr, tid, rank, part0, part1);
                __syncthreads();
                if (tid < 64) {
                    int ch = rank * 64 + tid;
#pragma unroll
                    for (int j = 0; j < 2; j++) {
                        if (!gp[j]) continue;
                        const float* xw = &g_tokxw[1][bpush_[j]][0];
                        float z = sigm(xw[ch] + SHU[j][ch]);
                        float r = sigm(xw[HH + ch] + SHU[j][HH + ch]);
                        float n = tanhf(xw[2 * HH + ch] + r * SHU[j][2 * HH + ch]);
                        float h = (1.f - z) * BUFH[j][ch] + z * n;
                        BUFH[j][ch] = h;
                        st_peer3(bufh_a[j] + (unsigned)ch * 4, rank, h);
                    }
                }
            }
        }

        // ---- action GRU ----
        if (t > 0) {
            mvq_pair(aU, AH[0], AH[1], SHU[0], SHU[1], nullptr, tid, rank, part0, part1);
            __syncthreads();
            if (tid < 64) {
                int ch = rank * 64 + tid;
#pragma unroll
                for (int j = 0; j < 2; j++) {
                    const float* xw = &g_tokxw[0][la_[j]][0];
                    float z = sigm(xw[ch] + SHU[j][ch]);
                    float r = sigm(xw[HH + ch] + SHU[j][HH + ch]);
                    float n = tanhf(xw[2 * HH + ch] + r * SHU[j][2 * HH + ch]);
                    float h = (1.f - z) * AH[j][ch] + z * n;
                    AH[j][ch] = h;
                    st_peer3(ah_a[j] + (unsigned)ch * 4, rank, h);
                }
            }
        } else {
            __syncthreads();
#pragma unroll
            for (int j = 0; j < 2; j++) {
                const float* xw = &g_tokxw[0][la_[j]][0];
                AH[j][tid] = sigm(xw[tid]) * tanhf(xw[2 * HH + tid]);
            }
        }
        CLUSTER_SYNC();   // all state quarters exchanged; full states local

        // ---- attention with dirty-tracked [256,256] pieces of Wc ----
        {
            bool dirty[2], acts[2], zero[2];
#pragma unroll
            for (int j = 0; j < 2; j++) {
                dirty[j] = (stop_[j] != prev_stop[j]) || (sslot_[j] >= 0);
                acts[j] = dirty[j] && stop_[j] >= 0;
                zero[j] = dirty[j] && stop_[j] < 0;
            }
            if (acts[0] || acts[1])
                pieceq_pair(Wc, acts[0] ? &HS[0][stop_[0] * HH] : HRED[0],
                                acts[1] ? &HS[1][stop_[1] * HH] : HRED[1],
                            PS[0], PS[1], acts[0], acts[1], tid, rank, part0, part1);
            if (tid < 64) {
                if (zero[0]) PS[0][tid] = 0.f;
                if (zero[1]) PS[1][tid] = 0.f;
            }
            pieceq_pair(Wc + (size_t)HH * HH, AH[0], AH[1], PAH[0], PAH[1],
                        true, true, tid, rank, part0, part1);
            bool db[2] = {t == 0 || bpush_[0] >= 0, t == 0 || bpush_[1] >= 0};
            if (db[0] || db[1])
                pieceq_pair(Wc + (size_t)2 * HH * HH, BUFH[0], BUFH[1], PB[0], PB[1],
                            db[0], db[1], tid, rank, part0, part1);
            if (tid < 64) {
                int ch = rank * 64 + tid;
                float bcv = __ldg(bc + ch);
#pragma unroll
                for (int j = 0; j < 2; j++) {
                    float v = PS[j][tid] + PAH[j][tid] + PB[j][tid] + bcv;
                    g_attT[ch][BL[j] * TT + t] = tanhf(v);
                }
            }
            prev_stop[0] = stop_[0]; prev_stop[1] = stop_[1];
        }
        CLUSTER_SYNC();   // protect state reads from next step's peer writes
    }
}

// ---------------- logits GEMM (round-5 body) + fused argmax ----------------
#define GBM 128
#define GBN 128
#define GBK 16
__global__ __launch_bounds__(256, 2) void gemm_kernel(const float* __restrict__ Wp,
                                                      const float* __restrict__ bp,
                                                      float* __restrict__ out) {
    __shared__ float As[2][GBK][GBM];
    __shared__ float Bs[2][GBK][GBN];
    int tid = threadIdx.x;
    int c0 = blockIdx.x * GBN;
    int row0 = blockIdx.y * GBM;
    const int MROWS = BB * TT;
    const float* attT = &g_attT[0][0];

    unsigned sA = smem_u32(&As[0][0][0]);
    unsigned sB = smem_u32(&Bs[0][0][0]);

    int ty = tid >> 4, tx = tid & 15;

    unsigned long long accp[8][4];
#pragma unroll
    for (int i = 0; i < 8; i++)
#pragma unroll
        for (int j = 0; j < 4; j++) accp[i][j] = 0ull;

    const int NTILE = HH / GBK;

#define ISSUE_TILE(buf, kk) do {                                              \
        _Pragma("unroll")                                                     \
        for (int i_ = 0; i_ < 2; i_++) {                                      \
            int idx_ = tid * 2 + i_;                                          \
            int k_ = idx_ >> 5;                                               \
            int q_ = idx_ & 31;                                               \
            unsigned da_ = sA + (unsigned)((((buf) * GBK + k_) * GBM + q_ * 4) * 4); \
            CP16(da_, attT + (size_t)((kk) + k_) * ATP + row0 + q_ * 4);      \
            int gc_ = c0 + q_ * 4;                                            \
            if (gc_ + 3 < VV) {                                               \
                unsigned db_ = sB + (unsigned)((((buf) * GBK + k_) * GBN + q_ * 4) * 4); \
                CP16(db_, Wp + (size_t)((kk) + k_) * VV + gc_);               \
            } else {                                                          \
                *(float4*)&Bs[buf][k_][q_ * 4] = make_float4(0.f, 0.f, 0.f, 0.f); \
            }                                                                 \
        }                                                                     \
        CP_COMMIT();                                                          \
    } while (0)

    ISSUE_TILE(0, 0);
    for (int tIdx = 0; tIdx < NTILE; tIdx++) {
        int buf = tIdx & 1;
        if (tIdx + 1 < NTILE) {
            ISSUE_TILE((tIdx + 1) & 1, (tIdx + 1) * GBK);
            asm volatile("cp.async.wait_group 1;" ::: "memory");
        } else {
            asm volatile("cp.async.wait_group 0;" ::: "memory");
        }
        __syncthreads();
#pragma unroll
        for (int k = 0; k < GBK; k++) {
            float4 a01 = *((const float4*)&As[buf][k][ty * 8]);
            float4 a23 = *((const float4*)&As[buf][k][ty * 8 + 4]);
            const ulonglong2* brow = (const ulonglong2*)&Bs[buf][k][tx * 8];
            ulonglong2 b01 = brow[0];
            ulonglong2 b23 = brow[1];
            unsigned long long brp[4] = {b01.x, b01.y, b23.x, b23.y};
            float ar[8] = {a01.x, a01.y, a01.z, a01.w, a23.x, a23.y, a23.z, a23.w};
#pragma unroll
            for (int i = 0; i < 8; i++) {
                unsigned long long ap = pk2(ar[i], ar[i]);
                ffma2(accp[i][0], ap, brp[0]);
                ffma2(accp[i][1], ap, brp[1]);
                ffma2(accp[i][2], ap, brp[2]);
                ffma2(accp[i][3], ap, brp[3]);
            }
        }
        __syncthreads();
    }

    float bias[8];
#pragma unroll
    for (int j = 0; j < 8; j++) {
        int gc = c0 + tx * 8 + j;
        bias[j] = (gc < VV) ? __ldg(bp + gc) : 0.f;
    }
#pragma unroll
    for (int i = 0; i < 8; i++) {
        int grow = row0 + ty * 8 + i;
        if (grow >= MROWS) continue;
        int gc = c0 + tx * 8;
        float acc[8];
#pragma unroll
        for (int j = 0; j < 4; j++) upk2(acc[2 * j], acc[2 * j + 1], accp[i][j]);
#pragma unroll
        for (int j = 0; j < 8; j++) acc[j] += bias[j];
        if (gc + 7 < VV) {
            float4 o0 = make_float4(acc[0], acc[1], acc[2], acc[3]);
            float4 o1 = make_float4(acc[4], acc[5], acc[6], acc[7]);
            *((float4*)(out + (size_t)grow * VV + gc)) = o0;
            *((float4*)(out + (size_t)grow * VV + gc + 4)) = o1;
        } else {
#pragma unroll
            for (int j = 0; j < 8; j++)
                if (gc + j < VV) out[(size_t)grow * VV + gc + j] = acc[j];
        }
        // fused argmax
        float rbest = -3.4e38f;
        int rbi = 0;
#pragma unroll
        for (int j = 0; j < 8; j++) {
            int gcj = gc + j;
            float v = (gcj < VV) ? acc[j] : -3.4e38f;
            if (v > rbest) { rbest = v; rbi = gcj; }
        }
#pragma unroll
        for (int o = 8; o > 0; o >>= 1) {
            float ov = __shfl_xor_sync(0xffffffffu, rbest, o);
            int oi = __shfl_xor_sync(0xffffffffu, rbi, o);
            if (ov > rbest || (ov == rbest && oi < rbi)) { rbest = ov; rbi = oi; }
        }
        if (tx == 0) {
            unsigned u = __float_as_uint(rbest);
            unsigned m = (u & 0x80000000u) ? ~u : (u | 0x80000000u);
            unsigned long long key =
                ((unsigned long long)m << 32) | (unsigned long long)(0xFFFFFFFFu - (unsigned)rbi);
            atomicMax(&g_amax[grow], key);
        }
    }
}

// ---------------- decode preds from argmax keys ----------------
__global__ void preds_kernel(float* __restrict__ preds) {
    int r = blockIdx.x * 256 + threadIdx.x;
    if (r < BB * TT) {
        unsigned long long k = g_amax[r];
        preds[r] = (float)(0xFFFFFFFFu - (unsigned)(k & 0xFFFFFFFFull));
    }
}

// ---------------- launch ----------------
extern "C" void kernel_launch(void* const* d_in, const int* in_sizes, int n_in,
                              void* d_out, int out_size) {
    const int*   actions = (const int*)d_in[0];
    const float* embed = (const float*)d_in[1];
    const float* aW = (const float*)d_in[2];
    const float* aU = (const float*)d_in[3];
    const float* ab = (const float*)d_in[4];
    const float* bW = (const float*)d_in[5];
    const float* bU = (const float*)d_in[6];
    const float* bb = (const float*)d_in[7];
    const float* sW = (const float*)d_in[8];
    const float* sU = (const float*)d_in[9];
    const float* sb = (const float*)d_in[10];
    const float* rW = (const float*)d_in[11];
    const float* rU = (const float*)d_in[12];
    const float* rb = (const float*)d_in[13];
    const float* Wc = (const float*)d_in[14];
    const float* bc = (const float*)d_in[15];
    const float* Wp = (const float*)d_in[16];
    const float* bp = (const float*)d_in[17];

    float* outf = (float*)d_out;
    size_t nl = (size_t)BB * TT * VV;
    float* preds = nullptr;
    float* logits;
    if ((size_t)out_size >= nl + (size_t)BB * TT) {
        preds = outf;
        logits = outf + BB * TT;
    } else {
        logits = outf;
    }

    control_kernel<<<1, 32>>>(actions);
    tokxw_kernel<<<dim3(NTOK, 4), 192>>>(embed, aW, ab, bW, bb, sW, sb, rW, rb);

    // smem floats: 4*8192 + 6*256 + 4*768 + 2*1536 + 6*64 = 40832
    size_t shbytes = 40832u * sizeof(float);
    cudaFuncSetAttribute(main_kernel, cudaFuncAttributeMaxDynamicSharedMemorySize, (int)shbytes);
    main_kernel<<<NPAIR * CL, 256, shbytes>>>(aU, bU, sU, rU, sW, sb, rW, rb, Wc, bc);

    dim3 gg((VV + GBN - 1) / GBN, (BB * TT + GBM - 1) / GBM);
    gemm_kernel<<<gg, 256>>>(Wp, bp, logits);
    if (preds) preds_kernel<<<(BB * TT + 255) / 256, 256>>>(preds);
}

// round 10
// speedup vs baseline: 3.0956x; 1.2937x over previous
#include <cuda_runtime.h>
#include <math.h>

#define BB 32
#define SS 32
#define TT 31
#define HH 256
#define H3 768
#define VV 12000
#define NTOK 32
#define BOUND 16
#define ATP 1024   // padded row length of g_attT (row = t*BB + b; rows >= 992 stay zero)
#define NPAIR 16   // lane pairs
#define CL 4       // CTAs per cluster (quarter-column split)
#define NMAIN (NPAIR * CL)          // 64 main CTAs
#define GBM 128
#define GBN 128
#define GBK 16
#define NCB ((VV + GBN - 1) / GBN)  // 94 column tiles
#define NTB 8                        // t-blocks of 128 rows

// ---------------- metadata (written by control kernel) ----------------
__device__ signed char g_la[TT][BB];
__device__ signed char g_npop[TT][BB];
__device__ signed char g_pop_slot[TT][BB][SS];
__device__ signed char g_pop_tok[TT][BB][SS];
__device__ signed char g_spush_slot[TT][BB];   // -1 none
__device__ signed char g_spush_tok[TT][BB];    // -1 = rfinal value, >=0 token
__device__ signed char g_bpush_tok[TT][BB];    // -1 none
__device__ signed char g_stop[TT][BB];         // stack top after step

// precomputed token xw tables: set 0=a,1=b,2=s,3=r
__device__ __align__(16) float g_tokxw[4][NTOK][H3];
// attention outputs TRANSPOSED: [hidden c][row], row = t*BB + b
__device__ __align__(16) float g_attT[HH][ATP];
// fused argmax accumulators + per-step completion flags (reset every launch)
__device__ unsigned long long g_amax[BB * TT];
__device__ int g_tdone[TT];

// ---------------- small asm helpers ----------------
__device__ __forceinline__ unsigned long long pk2(float lo, float hi) {
    unsigned long long r;
    asm("mov.b64 %0, {%1, %2};" : "=l"(r) : "f"(lo), "f"(hi));
    return r;
}
__device__ __forceinline__ void upk2(float& lo, float& hi, unsigned long long v) {
    asm("mov.b64 {%0, %1}, %2;" : "=f"(lo), "=f"(hi) : "l"(v));
}
__device__ __forceinline__ void ffma2(unsigned long long& d, unsigned long long a,
                                      unsigned long long b) {
    asm("fma.rn.f32x2 %0, %1, %2, %3;" : "=l"(d) : "l"(a), "l"(b), "l"(d));
}
__device__ __forceinline__ unsigned smem_u32(const void* p) {
    return (unsigned)__cvta_generic_to_shared(p);
}
__device__ __forceinline__ void st_peer(unsigned addr, unsigned peer, float v) {
    unsigned pa;
    asm volatile("mapa.shared::cluster.u32 %0, %1, %2;" : "=r"(pa) : "r"(addr), "r"(peer));
    asm volatile("st.shared::cluster.f32 [%0], %1;" :: "r"(pa), "f"(v) : "memory");
}
__device__ __forceinline__ void st_peer3(unsigned addr, int rank, float v) {
    st_peer(addr, (unsigned)((rank + 1) & 3), v);
    st_peer(addr, (unsigned)((rank + 2) & 3), v);
    st_peer(addr, (unsigned)((rank + 3) & 3), v);
}
#define CLUSTER_SYNC() do { \
    asm volatile("barrier.cluster.arrive.aligned;" ::: "memory"); \
    asm volatile("barrier.cluster.wait.aligned;" ::: "memory"); } while (0)

#define CP16(dst, src) \
    asm volatile("cp.async.cg.shared.global [%0], [%1], 16;" :: "r"(dst), "l"(src))
#define CP_COMMIT() asm volatile("cp.async.commit_group;" ::: "memory")

__device__ __forceinline__ float sigm(float v) { return 1.f / (1.f + expf(-v)); }

// ---------------- control kernel: pure integer RNNG simulation ----------------
__global__ void control_kernel(const int* __restrict__ actions) {
    int b = threadIdx.x;
    for (int r = b; r < BB * TT; r += 32) g_amax[r] = 0ull;
    if (b < TT) g_tdone[b] = 0;
    int st = -1, tt_ = -1, bt = 0, acc = 1;
    signed char tm[SS];
    signed char stok[SS];

    for (int t = 0; t < TT; t++) {
        int a = actions[b * SS + t];
        int la = a * acc;
        int is_red = (la == 2) ? 1 : 0;
        int is_nt  = (la > 2 && la < BOUND) ? 1 : 0;
        int is_gen = (la >= BOUND) ? 1 : 0;

        int np = 0;
        int ir = is_red, aok = 1;
        for (int i = 0; i < SS; i++) {
            if (!(ir && aok)) break;
            int can1 = (st >= 0);
            int pslot = -1;
            if (can1) { pslot = st; st--; }
            aok = aok & can1;
            int tag = 0;
            if (ir && aok) {
                int can2 = (tt_ >= 0);
                if (can2) { tag = tm[tt_]; tt_--; }
                aok = aok & can2;
            }
            int outm = ir & aok;
            if (outm) {
                g_pop_slot[t][b][np] = (signed char)pslot;
                g_pop_tok[t][b][np]  = stok[pslot];
                np++;
            }
            ir = (ir - tag) * aok;
        }
        int racc = aok;
        int sslot = -1, stokv = -2;
        if (is_red && racc) {
            int can = (st + 1 < SS);
            if (can) { st++; sslot = st; stokv = -1; stok[st] = -1; }
            racc &= can;
            if (racc) {
                int can2 = (tt_ + 1 < SS);
                if (can2) { tt_++; tm[tt_] = 0; }
                racc &= can2;
            }
        }
        unsigned ball = __ballot_sync(0xffffffffu, is_red);
        int tot = np;
        for (int o = 16; o > 0; o >>= 1) tot += __shfl_xor_sync(0xffffffffu, tot, o);
        int red_mult = 1;
        if (ball) red_mult = (tot == 0) ? 0 : racc;
        acc *= red_mult;

        if (is_nt) {
            int s5 = (st + 1 < SS);
            if (s5) { st++; stok[st] = (signed char)la; sslot = st; stokv = la; }
            acc *= s5;
            if (s5) {
                int s6 = (tt_ + 1 < SS);
                if (s6) { tt_++; tm[tt_] = 1; }
                acc *= s6;
            }
        }
        int bpush = -1;
        if (is_gen) {
            int s7 = (st + 1 < SS);
            if (s7) { st++; stok[st] = (signed char)la; sslot = st; stokv = la; }
            acc *= s7;
            int s8 = 1;
            if (s7) {
                s8 = (tt_ + 1 < SS);
                if (s8) { tt_++; tm[tt_] = 0; }
                acc *= s8;
            }
            if (s7 && s8) {
                int s9 = (bt + 1 < SS);
                if (s9) { bt++; bpush = la; }
                acc *= s9;
            }
        }
        g_bpush_tok[t][b]  = (signed char)bpush;
        g_la[t][b]         = (signed char)la;
        g_npop[t][b]       = (signed char)np;
        g_spush_slot[t][b] = (signed char)sslot;
        g_spush_tok[t][b]  = (signed char)stokv;
        g_stop[t][b]       = (signed char)st;
    }
}

// ---------------- token xw tables ----------------
__global__ void tokxw_kernel(const float* __restrict__ embed,
                             const float* __restrict__ aW, const float* __restrict__ ab,
                             const float* __restrict__ bW, const float* __restrict__ bb,
                             const float* __restrict__ sW, const float* __restrict__ sb,
                             const float* __restrict__ rW, const float* __restrict__ rb) {
    int tok = blockIdx.x;
    int set = blockIdx.y;
    const float* W  = (set == 0) ? aW : (set == 1) ? bW : (set == 2) ? sW : rW;
    const float* bi = (set == 0) ? ab : (set == 1) ? bb : (set == 2) ? sb : rb;
    int tid = threadIdx.x;  // 192 threads
    const float4* W4 = (const float4*)W;
    float4 acc = __ldg((const float4*)bi + tid);
    const float* x = embed + (size_t)tok * HH;
#pragma unroll 8
    for (int k = 0; k < HH; k++) {
        float xk = __ldg(x + k);
        float4 w = __ldg(W4 + k * 192 + tid);
        acc.x += xk * w.x; acc.y += xk * w.y; acc.z += xk * w.z; acc.w += xk * w.w;
    }
    ((float4*)(&g_tokxw[set][tok][0]))[tid] = acc;
}

// ---------------- quarter matvec for a LANE PAIR ----------------
__device__ __forceinline__ void mvq_pair(const float* __restrict__ M,
                                         const float* __restrict__ x0,
                                         const float* __restrict__ x1,
                                         float* out0, float* out1,
                                         const float* __restrict__ bias,
                                         int tid, int rank,
                                         float* part0, float* part1) {
    __syncthreads();
    int w = tid >> 5, l = tid & 31;
    const float* xs0 = x0 + w * 32;
    const float* xs1 = x1 + w * 32;
    const float4* Mrow = (const float4*)M + (size_t)(w * 32) * 192;
    int col0 = (l >> 4) * 64 + rank * 16 + (l & 15);
    int col1 = 128 + rank * 16 + l;
    float4 a0 = make_float4(0.f, 0.f, 0.f, 0.f), b0 = a0, a1 = a0, b1 = a0;
#pragma unroll 4
    for (int k = 0; k < 32; k++) {
        float x0k = xs0[k], x1k = xs1[k];
        float4 m0 = __ldg(Mrow + k * 192 + col0);
        a0.x += x0k * m0.x; a0.y += x0k * m0.y; a0.z += x0k * m0.z; a0.w += x0k * m0.w;
        b0.x += x1k * m0.x; b0.y += x1k * m0.y; b0.z += x1k * m0.z; b0.w += x1k * m0.w;
        if (l < 16) {
            float4 m1 = __ldg(Mrow + k * 192 + col1);
            a1.x += x0k * m1.x; a1.y += x0k * m1.y; a1.z += x0k * m1.z; a1.w += x0k * m1.w;
            b1.x += x1k * m1.x; b1.y += x1k * m1.y; b1.z += x1k * m1.z; b1.w += x1k * m1.w;
        }
    }
    float4* p40 = (float4*)part0 + w * 48;
    float4* p41 = (float4*)part1 + w * 48;
    p40[l] = a0; p41[l] = b0;
    if (l < 16) { p40[32 + l] = a1; p41[32 + l] = b1; }
    __syncthreads();
    if (tid < 192) {
        float s0 = 0.f, s1 = 0.f;
#pragma unroll
        for (int w2 = 0; w2 < 8; w2++) { s0 += part0[w2 * 192 + tid]; s1 += part1[w2 * 192 + tid]; }
        int f4i = tid >> 2;
        int g = f4i >> 4, o = f4i & 15;
        int gc = g * 256 + rank * 64 + o * 4 + (tid & 3);
        if (bias) { float bv = __ldg(bias + gc); s0 += bv; s1 += bv; }
        out0[gc] = s0; out1[gc] = s1;
    }
}

// quarter attention piece for a lane pair: out_j[0..63] = (x_j @ Wp)[rank*64 .. +64)
__device__ __forceinline__ void pieceq_pair(const float* __restrict__ Wp,
                                            const float* __restrict__ x0,
                                            const float* __restrict__ x1,
                                            float* out0, float* out1,
                                            bool act0, bool act1,
                                            int tid, int rank,
                                            float* part0, float* part1) {
    __syncthreads();
    int w = tid >> 5, l = tid & 31;
    if (l < 16) {
        const float* xs0 = x0 + w * 32;
        const float* xs1 = x1 + w * 32;
        const float4* W4 = (const float4*)Wp + (size_t)(w * 32) * 64 + rank * 16 + l;
        float4 a = make_float4(0.f, 0.f, 0.f, 0.f), b = a;
#pragma unroll 4
        for (int k = 0; k < 32; k++) {
            float4 m = __ldg(W4 + k * 64);
            float x0k = xs0[k], x1k = xs1[k];
            a.x += x0k * m.x; a.y += x0k * m.y; a.z += x0k * m.z; a.w += x0k * m.w;
            b.x += x1k * m.x; b.y += x1k * m.y; b.z += x1k * m.z; b.w += x1k * m.w;
        }
        ((float4*)part0)[w * 16 + l] = a;
        ((float4*)part1)[w * 16 + l] = b;
    }
    __syncthreads();
    if (tid < 64) {
        float s0 = 0.f, s1 = 0.f;
#pragma unroll
        for (int w2 = 0; w2 < 8; w2++) { s0 += part0[w2 * 64 + tid]; s1 += part1[w2 * 64 + tid]; }
        if (act0) out0[tid] = s0;
        if (act1) out1[tid] = s1;
    }
}

// ---------------- fused kernel: 64 main CTAs + 752 overlapped GEMM CTAs ----------------
extern __shared__ float smem_f[];
__global__ __launch_bounds__(256) __cluster_dims__(CL, 1, 1)
void main_kernel(
    const float* __restrict__ aU, const float* __restrict__ bU,
    const float* __restrict__ sU, const float* __restrict__ rU,
    const float* __restrict__ sW, const float* __restrict__ sb,
    const float* __restrict__ rW, const float* __restrict__ rb,
    const float* __restrict__ Wc, const float* __restrict__ bc,
    const float* __restrict__ Wp, const float* __restrict__ bp,
    float* __restrict__ out) {
    int tid = threadIdx.x;

    if (blockIdx.x >= NMAIN) {
        // ============ overlapped GEMM tile CTA ============
        int tileIdx = blockIdx.x - NMAIN;
        int tb = tileIdx / NCB;      // t-block 0..7 (slow dim -> early CTAs get early t)
        int cb = tileIdx % NCB;
        int row0 = tb * GBM;
        int c0 = cb * GBN;
        int tlast = 4 * tb + 3; if (tlast > TT - 1) tlast = TT - 1;

        // wait until all 64 main CTAs finished step tlast (steps complete in order)
        if (tid == 0) {
            while (atomicAdd(&g_tdone[tlast], 0) < NMAIN) __nanosleep(256);
        }
        __syncthreads();

        float* As = smem_f;                    // [2][GBK][GBM]
        float* Bs = smem_f + 2 * GBK * GBM;    // [2][GBK][GBN]
        const float* attT = &g_attT[0][0];
        unsigned sA = smem_u32(As);
        unsigned sB = smem_u32(Bs);
        int ty = tid >> 4, tx = tid & 15;

        unsigned long long accp[8][4];
#pragma unroll
        for (int i = 0; i < 8; i++)
#pragma unroll
            for (int j = 0; j < 4; j++) accp[i][j] = 0ull;

        const int NTILE = HH / GBK;

#define ISSUE_TILE(buf, kk) do {                                              \
        _Pragma("unroll")                                                     \
        for (int i_ = 0; i_ < 2; i_++) {                                      \
            int idx_ = tid * 2 + i_;                                          \
            int k_ = idx_ >> 5;                                               \
            int q_ = idx_ & 31;                                               \
            unsigned da_ = sA + (unsigned)((((buf) * GBK + k_) * GBM + q_ * 4) * 4); \
            CP16(da_, attT + (size_t)((kk) + k_) * ATP + row0 + q_ * 4);      \
            int gc_ = c0 + q_ * 4;                                            \
            if (gc_ + 3 < VV) {                                               \
                unsigned db_ = sB + (unsigned)((((buf) * GBK + k_) * GBN + q_ * 4) * 4); \
                CP16(db_, Wp + (size_t)((kk) + k_) * VV + gc_);               \
            } else {                                                          \
                *(float4*)&Bs[((buf) * GBK + k_) * GBN + q_ * 4] =            \
                    make_float4(0.f, 0.f, 0.f, 0.f);                          \
            }                                                                 \
        }                                                                     \
        CP_COMMIT();                                                          \
    } while (0)

        ISSUE_TILE(0, 0);
        for (int tIdx = 0; tIdx < NTILE; tIdx++) {
            int buf = tIdx & 1;
            if (tIdx + 1 < NTILE) {
                ISSUE_TILE((tIdx + 1) & 1, (tIdx + 1) * GBK);
                asm volatile("cp.async.wait_group 1;" ::: "memory");
            } else {
                asm volatile("cp.async.wait_group 0;" ::: "memory");
            }
            __syncthreads();
#pragma unroll
            for (int k = 0; k < GBK; k++) {
                float4 a01 = *((const float4*)&As[(buf * GBK + k) * GBM + ty * 8]);
                float4 a23 = *((const float4*)&As[(buf * GBK + k) * GBM + ty * 8 + 4]);
                const ulonglong2* brow = (const ulonglong2*)&Bs[(buf * GBK + k) * GBN + tx * 8];
                ulonglong2 b01 = brow[0];
                ulonglong2 b23 = brow[1];
                unsigned long long brp[4] = {b01.x, b01.y, b23.x, b23.y};
                float ar[8] = {a01.x, a01.y, a01.z, a01.w, a23.x, a23.y, a23.z, a23.w};
#pragma unroll
                for (int i = 0; i < 8; i++) {
                    unsigned long long ap = pk2(ar[i], ar[i]);
                    ffma2(accp[i][0], ap, brp[0]);
                    ffma2(accp[i][1], ap, brp[1]);
                    ffma2(accp[i][2], ap, brp[2]);
                    ffma2(accp[i][3], ap, brp[3]);
                }
            }
            __syncthreads();
        }

        float bias[8];
#pragma unroll
        for (int j = 0; j < 8; j++) {
            int gc = c0 + tx * 8 + j;
            bias[j] = (gc < VV) ? __ldg(bp + gc) : 0.f;
        }
#pragma unroll
        for (int i = 0; i < 8; i++) {
            int grow = row0 + ty * 8 + i;          // t*BB + b index
            if (grow >= BB * TT) continue;          // pad rows
            int tt2 = grow >> 5, bb2 = grow & 31;
            int orow = bb2 * TT + tt2;              // output row b*TT + t
            int gc = c0 + tx * 8;
            float acc[8];
#pragma unroll
            for (int j = 0; j < 4; j++) upk2(acc[2 * j], acc[2 * j + 1], accp[i][j]);
#pragma unroll
            for (int j = 0; j < 8; j++) acc[j] += bias[j];
            if (gc + 7 < VV) {
                float4 o0 = make_float4(acc[0], acc[1], acc[2], acc[3]);
                float4 o1 = make_float4(acc[4], acc[5], acc[6], acc[7]);
                *((float4*)(out + (size_t)orow * VV + gc)) = o0;
                *((float4*)(out + (size_t)orow * VV + gc + 4)) = o1;
            } else {
#pragma unroll
                for (int j = 0; j < 8; j++)
                    if (gc + j < VV) out[(size_t)orow * VV + gc + j] = acc[j];
            }
            float rbest = -3.4e38f;
            int rbi = 0;
#pragma unroll
            for (int j = 0; j < 8; j++) {
                int gcj = gc + j;
                float v = (gcj < VV) ? acc[j] : -3.4e38f;
                if (v > rbest) { rbest = v; rbi = gcj; }
            }
#pragma unroll
            for (int o = 8; o > 0; o >>= 1) {
                float ov = __shfl_xor_sync(0xffffffffu, rbest, o);
                int oi = __shfl_xor_sync(0xffffffffu, rbi, o);
                if (ov > rbest || (ov == rbest && oi < rbi)) { rbest = ov; rbi = oi; }
            }
            if (tx == 0) {
                unsigned u = __float_as_uint(rbest);
                unsigned m = (u & 0x80000000u) ? ~u : (u | 0x80000000u);
                unsigned long long key =
                    ((unsigned long long)m << 32) | (unsigned long long)(0xFFFFFFFFu - (unsigned)rbi);
                atomicMax(&g_amax[orow], key);
            }
        }
        return;
    }

    // ============ main (stack system) CTA: 2 lanes per 4-CTA cluster ============
    int p = blockIdx.x >> 2;
    int rank = blockIdx.x & 3;
    int b0 = p, b1 = p + NPAIR;

    float* sm_v0 = smem_f;               // 8192
    float* sm_v1 = sm_v0 + 8192;
    float* hs0   = sm_v1 + 8192;         // 8192
    float* hs1   = hs0 + 8192;
    float* bufh0 = hs1 + 8192;
    float* bufh1 = bufh0 + 256;
    float* ah0   = bufh1 + 256;
    float* ah1   = ah0 + 256;
    float* hred0 = ah1 + 256;
    float* hred1 = hred0 + 256;
    float* s_hu0 = hred1 + 256;          // 768
    float* s_hu1 = s_hu0 + 768;
    float* s_xw0 = s_hu1 + 768;
    float* s_xw1 = s_xw0 + 768;
    float* part0 = s_xw1 + 768;          // 1536
    float* part1 = part0 + 1536;
    float* p_s0  = part1 + 1536;         // 64 each
    float* p_s1  = p_s0 + 64;
    float* p_ah0 = p_s1 + 64;
    float* p_ah1 = p_ah0 + 64;
    float* p_b0  = p_ah1 + 64;
    float* p_b1  = p_b0 + 64;

    unsigned base_u32 = smem_u32(smem_f);
    unsigned hred_a[2], hs_a[2], bufh_a[2], ah_a[2];
    hred_a[0] = base_u32 + (unsigned)((char*)hred0 - (char*)smem_f);
    hred_a[1] = base_u32 + (unsigned)((char*)hred1 - (char*)smem_f);
    hs_a[0]   = base_u32 + (unsigned)((char*)hs0 - (char*)smem_f);
    hs_a[1]   = base_u32 + (unsigned)((char*)hs1 - (char*)smem_f);
    bufh_a[0] = base_u32 + (unsigned)((char*)bufh0 - (char*)smem_f);
    bufh_a[1] = base_u32 + (unsigned)((char*)bufh1 - (char*)smem_f);
    ah_a[0]   = base_u32 + (unsigned)((char*)ah0 - (char*)smem_f);
    ah_a[1]   = base_u32 + (unsigned)((char*)ah1 - (char*)smem_f);

    float* SMV[2]  = {sm_v0, sm_v1};
    float* HS[2]   = {hs0, hs1};
    float* BUFH[2] = {bufh0, bufh1};
    float* AH[2]   = {ah0, ah1};
    float* HRED[2] = {hred0, hred1};
    float* SHU[2]  = {s_hu0, s_hu1};
    float* SXW[2]  = {s_xw0, s_xw1};
    float* PS[2]   = {p_s0, p_s1};
    float* PAH[2]  = {p_ah0, p_ah1};
    float* PB[2]   = {p_b0, p_b1};
    int BL[2] = {b0, b1};

    {
        const float* xw = &g_tokxw[1][1][0];
        float v = sigm(xw[tid]) * tanhf(xw[2 * HH + tid]);
        bufh0[tid] = v; bufh1[tid] = v;
        if (tid < 64) { p_s0[tid] = 0.f; p_s1[tid] = 0.f; }
    }
    __syncthreads();

    int prev_stop[2] = {-1, -1};

    for (int t = 0; t < TT; t++) {
        int la_[2], np_[2], sslot_[2], stokv_[2], bpush_[2], stop_[2];
#pragma unroll
        for (int j = 0; j < 2; j++) {
            int bl = BL[j];
            la_[j]    = g_la[t][bl];
            np_[j]    = g_npop[t][bl];
            sslot_[j] = g_spush_slot[t][bl];
            stokv_[j] = g_spush_tok[t][bl];
            bpush_[j] = g_bpush_tok[t][bl];
            stop_[j]  = g_stop[t][bl];
        }
        int npmax = np_[0] > np_[1] ? np_[0] : np_[1];

        // ---- reduce chain ----
        for (int i = 0; i < npmax; i++) {
            bool act[2], needW[2];
            int tok[2], slot[2];
#pragma unroll
            for (int j = 0; j < 2; j++) {
                act[j] = (i < np_[j]);
                tok[j] = act[j] ? (int)g_pop_tok[t][BL[j]][i] : 0;
                slot[j] = act[j] ? (int)g_pop_slot[t][BL[j]][i] : 0;
                needW[j] = act[j] && tok[j] < 0;
            }
            if (needW[0] || needW[1])
                mvq_pair(rW, needW[0] ? &SMV[0][slot[0] * HH] : HRED[0],
                             needW[1] ? &SMV[1][slot[1] * HH] : HRED[1],
                         SXW[0], SXW[1], rb, tid, rank, part0, part1);
            if (i > 0)
                mvq_pair(rU, HRED[0], HRED[1], SHU[0], SHU[1], nullptr,
                         tid, rank, part0, part1);
            __syncthreads();
            if (tid < 64) {
                int ch = rank * 64 + tid;
#pragma unroll
                for (int j = 0; j < 2; j++) {
                    if (!act[j]) continue;
                    const float* xw = (tok[j] >= 0) ? &g_tokxw[3][tok[j]][0] : SXW[j];
                    float hz = 0.f, hr = 0.f, hn = 0.f, hp = 0.f;
                    if (i > 0) {
                        hz = SHU[j][ch]; hr = SHU[j][HH + ch]; hn = SHU[j][2 * HH + ch];
                        hp = HRED[j][ch];
                    }
                    float z = sigm(xw[ch] + hz);
                    float r = sigm(xw[HH + ch] + hr);
                    float n = tanhf(xw[2 * HH + ch] + r * hn);
                    float h = (1.f - z) * hp + z * n;
                    HRED[j][ch] = h;
                    st_peer3(hred_a[j] + (unsigned)ch * 4, rank, h);
                }
            }
            CLUSTER_SYNC();
        }

        // ---- stack push ----
        {
            bool red[2] = {sslot_[0] >= 0 && stokv_[0] == -1,
                           sslot_[1] >= 0 && stokv_[1] == -1};
            if (red[0]) SMV[0][sslot_[0] * HH + tid] = HRED[0][tid];
            if (red[1]) SMV[1][sslot_[1] * HH + tid] = HRED[1][tid];
            if (red[0] || red[1])
                mvq_pair(sW, HRED[0], HRED[1], SXW[0], SXW[1], sb, tid, rank, part0, part1);
            bool pu[2] = {sslot_[0] > 0, sslot_[1] > 0};
            if (pu[0] || pu[1])
                mvq_pair(sU, pu[0] ? &HS[0][(sslot_[0] - 1) * HH] : HRED[0],
                             pu[1] ? &HS[1][(sslot_[1] - 1) * HH] : HRED[1],
                         SHU[0], SHU[1], nullptr, tid, rank, part0, part1);
            __syncthreads();
            if (tid < 64) {
                int ch = rank * 64 + tid;
#pragma unroll
                for (int j = 0; j < 2; j++) {
                    if (sslot_[j] < 0) continue;
                    const float* xw = (stokv_[j] >= 0) ? &g_tokxw[2][stokv_[j]][0] : SXW[j];
                    float hz = 0.f, hr = 0.f, hn = 0.f, hp = 0.f;
                    if (sslot_[j] > 0) {
                        hz = SHU[j][ch]; hr = SHU[j][HH + ch]; hn = SHU[j][2 * HH + ch];
                        hp = HS[j][(sslot_[j] - 1) * HH + ch];
                    }
                    float z = sigm(xw[ch] + hz);
                    float r = sigm(xw[HH + ch] + hr);
                    float n = tanhf(xw[2 * HH + ch] + r * hn);
                    float h = (1.f - z) * hp + z * n;
                    HS[j][sslot_[j] * HH + ch] = h;
                    st_peer3(hs_a[j] + (unsigned)(sslot_[j] * HH + ch) * 4, rank, h);
                }
            }
        }

        // ---- buffer push (GEN) ----
        {
            bool gp[2] = {bpush_[0] >= 0, bpush_[1] >= 0};
            if (gp[0] || gp[1]) {
                mvq_pair(bU, BUFH[0], BUFH[1], SHU[0], SHU[1], nullptr, tid, rank, part0, part1);
                __syncthreads();
                if (tid < 64) {
                    int ch = rank * 64 + tid;
#pragma unroll
                    for (int j = 0; j < 2; j++) {
                        if (!gp[j]) continue;
                        const float* xw = &g_tokxw[1][bpush_[j]][0];
                        float z = sigm(xw[ch] + SHU[j][ch]);
                        float r = sigm(xw[HH + ch] + SHU[j][HH + ch]);
                        float n = tanhf(xw[2 * HH + ch] + r * SHU[j][2 * HH + ch]);
                        float h = (1.f - z) * BUFH[j][ch] + z * n;
                        BUFH[j][ch] = h;
                        st_peer3(bufh_a[j] + (unsigned)ch * 4, rank, h);
                    }
                }
            }
        }

        // ---- action GRU ----
        if (t > 0) {
            mvq_pair(aU, AH[0], AH[1], SHU[0], SHU[1], nullptr, tid, rank, part0, part1);
            __syncthreads();
            if (tid < 64) {
                int ch = rank * 64 + tid;
#pragma unroll
                for (int j = 0; j < 2; j++) {
                    const float* xw = &g_tokxw[0][la_[j]][0];
                    float z = sigm(xw[ch] + SHU[j][ch]);
                    float r = sigm(xw[HH + ch] + SHU[j][HH + ch]);
                    float n = tanhf(xw[2 * HH + ch] + r * SHU[j][2 * HH + ch]);
                    float h = (1.f - z) * AH[j][ch] + z * n;
                    AH[j][ch] = h;
                    st_peer3(ah_a[j] + (unsigned)ch * 4, rank, h);
                }
            }
        } else {
            __syncthreads();
#pragma unroll
            for (int j = 0; j < 2; j++) {
                const float* xw = &g_tokxw[0][la_[j]][0];
                AH[j][tid] = sigm(xw[tid]) * tanhf(xw[2 * HH + tid]);
            }
        }
        CLUSTER_SYNC();

        // ---- attention with dirty-tracked [256,256] pieces of Wc ----
        {
            bool dirty[2], acts[2], zero[2];
#pragma unroll
            for (int j = 0; j < 2; j++) {
                dirty[j] = (stop_[j] != prev_stop[j]) || (sslot_[j] >= 0);
                acts[j] = dirty[j] && stop_[j] >= 0;
                zero[j] = dirty[j] && stop_[j] < 0;
            }
            if (acts[0] || acts[1])
                pieceq_pair(Wc, acts[0] ? &HS[0][stop_[0] * HH] : HRED[0],
                                acts[1] ? &HS[1][stop_[1] * HH] : HRED[1],
                            PS[0], PS[1], acts[0], acts[1], tid, rank, part0, part1);
            if (tid < 64) {
                if (zero[0]) PS[0][tid] = 0.f;
                if (zero[1]) PS[1][tid] = 0.f;
            }
            pieceq_pair(Wc + (size_t)HH * HH, AH[0], AH[1], PAH[0], PAH[1],
                        true, true, tid, rank, part0, part1);
            bool db[2] = {t == 0 || bpush_[0] >= 0, t == 0 || bpush_[1] >= 0};
            if (db[0] || db[1])
                pieceq_pair(Wc + (size_t)2 * HH * HH, BUFH[0], BUFH[1], PB[0], PB[1],
                            db[0], db[1], tid, rank, part0, part1);
            if (tid < 64) {
                int ch = rank * 64 + tid;
                float bcv = __ldg(bc + ch);
#pragma unroll
                for (int j = 0; j < 2; j++) {
                    float v = PS[j][tid] + PAH[j][tid] + PB[j][tid] + bcv;
                    g_attT[ch][t * BB + BL[j]] = tanhf(v);   // row = t*BB + b
                }
            }
            prev_stop[0] = stop_[0]; prev_stop[1] = stop_[1];
        }
        // publish step completion for overlapped GEMM CTAs
        __syncthreads();
        if (tid == 0) { __threadfence(); atomicAdd(&g_tdone[t], 1); }
        CLUSTER_SYNC();
    }
}

// ---------------- decode preds from argmax keys ----------------
__global__ void preds_kernel(float* __restrict__ preds) {
    int r = blockIdx.x * 256 + threadIdx.x;
    if (r < BB * TT) {
        unsigned long long k = g_amax[r];
        preds[r] = (float)(0xFFFFFFFFu - (unsigned)(k & 0xFFFFFFFFull));
    }
}

// ---------------- launch ----------------
extern "C" void kernel_launch(void* const* d_in, const int* in_sizes, int n_in,
                              void* d_out, int out_size) {
    const int*   actions = (const int*)d_in[0];
    const float* embed = (const float*)d_in[1];
    const float* aW = (const float*)d_in[2];
    const float* aU = (const float*)d_in[3];
    const float* ab = (const float*)d_in[4];
    const float* bW = (const float*)d_in[5];
    const float* bU = (const float*)d_in[6];
    const float* bb = (const float*)d_in[7];
    const float* sW = (const float*)d_in[8];
    const float* sU = (const float*)d_in[9];
    const float* sb = (const float*)d_in[10];
    const float* rW = (const float*)d_in[11];
    const float* rU = (const float*)d_in[12];
    const float* rb = (const float*)d_in[13];
    const float* Wc = (const float*)d_in[14];
    const float* bc = (const float*)d_in[15];
    const float* Wp = (const float*)d_in[16];
    const float* bp = (const float*)d_in[17];

    float* outf = (float*)d_out;
    size_t nl = (size_t)BB * TT * VV;
    float* preds = nullptr;
    float* logits;
    if ((size_t)out_size >= nl + (size_t)BB * TT) {
        preds = outf;
        logits = outf + BB * TT;
    } else {
        logits = outf;
    }

    control_kernel<<<1, 32>>>(actions);
    tokxw_kernel<<<dim3(NTOK, 4), 192>>>(embed, aW, ab, bW, bb, sW, sb, rW, rb);

    // smem floats: 4*8192 + 6*256 + 4*768 + 2*1536 + 6*64 = 40832 (gemm needs 8192)
    size_t shbytes = 40832u * sizeof(float);
    cudaFuncSetAttribute(main_kernel, cudaFuncAttributeMaxDynamicSharedMemorySize, (int)shbytes);
    int grid = NMAIN + NTB * NCB;   // 64 + 752 = 816 (divisible by CL=4)
    main_kernel<<<grid, 256, shbytes>>>(aU, bU, sU, rU, sW, sb, rW, rb, Wc, bc,
                                        Wp, bp, logits);
    if (preds) preds_kernel<<<(BB * TT + 255) / 256, 256>>>(preds);
}